// round 1
// baseline (speedup 1.0000x reference)
#include <cuda_runtime.h>
#include <math.h>

// ---------------- problem constants ----------------
// B=16, CIN=COUT=128, H=W=64, E=8, PS=16, FF=8, GC=32, HID=64, HC=512
#define NB   16
#define NC   128
#define NH   64
#define NW   64
#define NE   8
#define NHC  512
#define HWSZ 4096    // 64*64

// ---------------- scratch (device globals; no allocation allowed) ----------
__device__ float g_z[67108864];     // [E][B][C][H][W] expert conv raw, 268MB
__device__ float g_comb[8388608];   // [B][C][H][W]
__device__ float g_h1[33554432];    // [B][HC][H][W] pw1 raw
__device__ float g_h2[33554432];    // [B][HC][H][W] dw raw
__device__ float g_h3[2097152];     // [B][C][32][32] pw2 raw
__device__ float g_wts[128];        // [16 patches][8 experts]
// partial sums (sum,sumsq interleaved) - every slot written every run -> deterministic
__device__ float g_part_exp[1024 * 32 * 2];   // slots=(e,b,g)=1024, nper=32 (h-pairs)
__device__ float g_ms_exp[1024 * 2];
__device__ float g_part1[128 * 64 * 2];       // slots=(b,g)=128, nper=64 (px tiles)
__device__ float g_ms1[128 * 2];
__device__ float g_part2[128 * 512 * 2];      // slots=(b,g)=128, nper=512 (ch%64 * 8 + htile)
__device__ float g_ms2[128 * 2];
__device__ float g_part3[128 * 16 * 2];       // slots=(b,g)=128, nper=16 (px tiles)
__device__ float g_ms3[128 * 2];

__device__ __forceinline__ float silu_f(float x) {
    return x / (1.0f + expf(-x));
}

// ---------------- K0: router (Fourier feats -> MLP -> softmax) --------------
__global__ void k_router(const float* __restrict__ w1, const float* __restrict__ b1,
                         const float* __restrict__ w2, const float* __restrict__ b2) {
    __shared__ float feats[16 * 32];
    __shared__ float hid[16 * 64];
    __shared__ float lg[16 * 8];
    int tid = threadIdx.x;  // 1024 threads
    if (tid < 512) {
        int p = tid >> 5, f = tid & 31;
        int py = p >> 2, px = p & 3;
        int k = f & 7, kind = f >> 3;
        float freq = exp2f((float)k) * 3.14159265358979323846f;
        float cy = (py + 0.5f) * 0.25f;
        float cx = (px + 0.5f) * 0.25f;
        float v;
        if (kind == 0)      v = sinf(cy * freq);
        else if (kind == 1) v = cosf(cy * freq);
        else if (kind == 2) v = sinf(cx * freq);
        else                v = cosf(cx * freq);
        feats[p * 32 + f] = v;
    }
    __syncthreads();
    {
        int p = tid >> 6, hh = tid & 63;
        float a = b1[hh];
        for (int f = 0; f < 32; f++) a += feats[p * 32 + f] * w1[f * 64 + hh];
        hid[p * 64 + hh] = silu_f(a);
    }
    __syncthreads();
    if (tid < 128) {
        int p = tid >> 3, e = tid & 7;
        float a = b2[e];
        for (int hh = 0; hh < 64; hh++) a += hid[p * 64 + hh] * w2[hh * 8 + e];
        lg[p * 8 + e] = a;
    }
    __syncthreads();
    if (tid < 16) {
        float mx = -1e30f;
        for (int e = 0; e < 8; e++) mx = fmaxf(mx, lg[tid * 8 + e]);
        float ex[8], s = 0.f;
        for (int e = 0; e < 8; e++) { ex[e] = expf(lg[tid * 8 + e] - mx); s += ex[e]; }
        float inv = 1.0f / s;
        for (int e = 0; e < 8; e++) g_wts[tid * 8 + e] = ex[e] * inv;
    }
}

// ---------------- K1: expert 3x3 convs (implicit direct conv) ---------------
// grid (16 oc-tiles, 32 h-pairs, 16 b); block 256 threads.
// Each block: 64 out-channels x 128 pixels (2 rows), 8px x 4oc per thread.
__global__ __launch_bounds__(256) void k_expert(const float* __restrict__ x,
                                                const float* __restrict__ w_exp) {
    __shared__ float smem[8192];
    __shared__ float red[512];
    int tid = threadIdx.x;
    int octile = blockIdx.x, hb = blockIdx.y, b = blockIdx.z;
    int e = octile >> 1;
    int ocE0 = (octile & 1) * 64;
    int pg = tid & 15, og = tid >> 4;
    int ro = pg >> 3;            // output row within pair (0/1)
    int ws = (pg & 7) * 8;       // starting w of this thread's 8 pixels

    float acc[32];
#pragma unroll
    for (int i = 0; i < 32; i++) acc[i] = 0.f;

    float* shin = smem;          // [4 rows][66]
    float* shw  = smem + 384;    // [64 oc][9]

    for (int c = 0; c < 128; c++) {
        __syncthreads();
        for (int idx = tid; idx < 264; idx += 256) {
            int r = idx / 66, i = idx % 66;
            int hh = 2 * hb - 1 + r, ww = i - 1;
            float v = 0.f;
            if (hh >= 0 && hh < 64 && ww >= 0 && ww < 64)
                v = x[((b * NC + c) * 64 + hh) * 64 + ww];
            shin[idx] = v;
        }
        for (int idx = tid; idx < 576; idx += 256) {
            int ocl = idx / 9, tap = idx % 9;
            shw[idx] = w_exp[(((e * NC + ocE0 + ocl) * NC) + c) * 9 + tap];
        }
        __syncthreads();
#pragma unroll
        for (int r = 0; r < 3; r++) {
            const float* ip = shin + (ro + r) * 66 + ws;
            float i0 = ip[0], i1 = ip[1], i2 = ip[2], i3 = ip[3], i4 = ip[4];
            float i5 = ip[5], i6 = ip[6], i7 = ip[7], i8 = ip[8], i9 = ip[9];
#pragma unroll
            for (int l = 0; l < 4; l++) {
                const float* wp = shw + (4 * og + l) * 9 + r * 3;
                float w0 = wp[0], w1 = wp[1], w2 = wp[2];
                acc[0 * 4 + l] += i0 * w0 + i1 * w1 + i2 * w2;
                acc[1 * 4 + l] += i1 * w0 + i2 * w1 + i3 * w2;
                acc[2 * 4 + l] += i2 * w0 + i3 * w1 + i4 * w2;
                acc[3 * 4 + l] += i3 * w0 + i4 * w1 + i5 * w2;
                acc[4 * 4 + l] += i4 * w0 + i5 * w1 + i6 * w2;
                acc[5 * 4 + l] += i5 * w0 + i6 * w1 + i7 * w2;
                acc[6 * 4 + l] += i6 * w0 + i7 * w1 + i8 * w2;
                acc[7 * 4 + l] += i7 * w0 + i8 * w1 + i9 * w2;
            }
        }
    }

    // ---- per-(e,b,group) partial stats, group = 16 channels -> seg of 64 threads
    float s1 = 0.f, s2 = 0.f;
#pragma unroll
    for (int i = 0; i < 32; i++) { s1 += acc[i]; s2 += acc[i] * acc[i]; }
    red[tid] = s1; red[256 + tid] = s2;
    __syncthreads();
    if ((tid & 63) == 0) {
        float a = 0.f, bq = 0.f;
        for (int i = 0; i < 64; i++) { a += red[tid + i]; bq += red[256 + tid + i]; }
        int seg = tid >> 6;
        int g = (octile & 1) * 4 + seg;
        int slot = (e * NB + b) * 8 + g;
        g_part_exp[(slot * 32 + hb) * 2 + 0] = a;
        g_part_exp[(slot * 32 + hb) * 2 + 1] = bq;
    }
    __syncthreads();
    // ---- stage for coalesced store
#pragma unroll
    for (int k = 0; k < 8; k++)
#pragma unroll
        for (int l = 0; l < 4; l++)
            smem[(4 * og + l) * 128 + ro * 64 + ws + k] = acc[k * 4 + l];
    __syncthreads();
    for (int idx = tid; idx < 8192; idx += 256) {
        int ocl = idx >> 7, p = idx & 127;
        int h = 2 * hb + (p >> 6), w = p & 63;
        g_z[((e * NB + b) * NC + ocE0 + ocl) * HWSZ + h * 64 + w] = smem[idx];
    }
}

// ---------------- finalize stats (selector-based) ---------------------------
__global__ void k_finalize(int which) {
    const float* part; float* ms; int nper, nslots; float invN;
    if (which == 0)      { part = g_part_exp; ms = g_ms_exp; nper = 32;  nslots = 1024; invN = 1.0f / 65536.0f; }
    else if (which == 1) { part = g_part1;    ms = g_ms1;    nper = 64;  nslots = 128;  invN = 1.0f / 262144.0f; }
    else if (which == 2) { part = g_part2;    ms = g_ms2;    nper = 512; nslots = 128;  invN = 1.0f / 262144.0f; }
    else                 { part = g_part3;    ms = g_ms3;    nper = 16;  nslots = 128;  invN = 1.0f / 16384.0f; }
    int s = blockIdx.x * blockDim.x + threadIdx.x;
    if (s >= nslots) return;
    float s1 = 0.f, s2 = 0.f;
    for (int i = 0; i < nper; i++) {
        s1 += part[(s * nper + i) * 2 + 0];
        s2 += part[(s * nper + i) * 2 + 1];
    }
    float m = s1 * invN;
    float v = s2 * invN - m * m;
    ms[s * 2 + 0] = m;
    ms[s * 2 + 1] = rsqrtf(v + 1e-5f);
}

// ---------------- K3: GN+SiLU+residual + patch-weighted combine -------------
__global__ __launch_bounds__(256) void k_combine(const float* __restrict__ x,
                                                 const float* __restrict__ gs,
                                                 const float* __restrict__ gb) {
    int idx = blockIdx.x * 256 + threadIdx.x;   // 8388608 total
    int w = idx & 63, h = (idx >> 6) & 63, c = (idx >> 12) & 127, b = idx >> 19;
    int patch = ((h >> 4) << 2) + (w >> 4);
    int g = c >> 4;
    float a = x[idx];
    int hw = idx & 4095;
#pragma unroll
    for (int e = 0; e < 8; e++) {
        float zv = g_z[((e * NB + b) * NC + c) * HWSZ + hw];
        float m  = g_ms_exp[(((e * NB + b) * 8) + g) * 2 + 0];
        float rs = g_ms_exp[(((e * NB + b) * 8) + g) * 2 + 1];
        float t = (zv - m) * rs * gs[e * NC + c] + gb[e * NC + c];
        a += g_wts[patch * 8 + e] * silu_f(t);
    }
    g_comb[idx] = a;
}

// ---------------- K4: pw1 1x1 conv 128->512 + stats --------------------------
// grid (8 hc-groups, 64 px-tiles, 16 b); block 256; 64px x 64hc, 4x4 per thread
__global__ __launch_bounds__(256) void k_pw1(const float* __restrict__ w_pw1) {
    __shared__ float sA[4096], sW[4096], red[512];
    int tid = threadIdx.x;
    int g = blockIdx.x, pt = blockIdx.y, b = blockIdx.z;
    int hc0 = g * 64, px0 = pt * 64;
    int pg = tid & 15, og = tid >> 4;
    float acc[16];
#pragma unroll
    for (int i = 0; i < 16; i++) acc[i] = 0.f;

    for (int c0 = 0; c0 < 128; c0 += 64) {
        __syncthreads();
        for (int idx = tid; idx < 4096; idx += 256) {
            int cc = idx >> 6, p = idx & 63;
            sA[idx] = g_comb[(b * NC + c0 + cc) * HWSZ + px0 + p];
        }
        for (int idx = tid; idx < 4096; idx += 256) {
            int hc = idx >> 6, cc = idx & 63;
            sW[idx] = w_pw1[(hc0 + hc) * NC + c0 + cc];
        }
        __syncthreads();
        for (int cc = 0; cc < 64; cc++) {
            float a0 = sA[cc * 64 + 4 * pg + 0];
            float a1 = sA[cc * 64 + 4 * pg + 1];
            float a2 = sA[cc * 64 + 4 * pg + 2];
            float a3 = sA[cc * 64 + 4 * pg + 3];
#pragma unroll
            for (int l = 0; l < 4; l++) {
                float wv = sW[(4 * og + l) * 64 + cc];
                acc[0 * 4 + l] += a0 * wv;
                acc[1 * 4 + l] += a1 * wv;
                acc[2 * 4 + l] += a2 * wv;
                acc[3 * 4 + l] += a3 * wv;
            }
        }
    }
    // stats (whole block = one (b,group))
    float s1 = 0.f, s2 = 0.f;
#pragma unroll
    for (int i = 0; i < 16; i++) { s1 += acc[i]; s2 += acc[i] * acc[i]; }
    red[tid] = s1; red[256 + tid] = s2;
    __syncthreads();
    for (int st = 128; st > 0; st >>= 1) {
        if (tid < st) { red[tid] += red[tid + st]; red[256 + tid] += red[256 + tid + st]; }
        __syncthreads();
    }
    if (tid == 0) {
        g_part1[((b * 8 + g) * 64 + pt) * 2 + 0] = red[0];
        g_part1[((b * 8 + g) * 64 + pt) * 2 + 1] = red[256];
    }
    __syncthreads();
#pragma unroll
    for (int k = 0; k < 4; k++)
#pragma unroll
        for (int l = 0; l < 4; l++)
            sA[(4 * og + l) * 64 + 4 * pg + k] = acc[k * 4 + l];
    __syncthreads();
    for (int idx = tid; idx < 4096; idx += 256) {
        int hcl = idx >> 6, p = idx & 63;
        g_h1[(b * NHC + hc0 + hcl) * HWSZ + px0 + p] = sA[idx];
    }
}

// ---------------- K6: depthwise 3x3 (normalize h1 on load) + stats ----------
// grid (8 h-tiles, 512 ch, 16 b); block 256
__global__ __launch_bounds__(256) void k_dw(const float* __restrict__ w_dw,
                                            const float* __restrict__ s1v,
                                            const float* __restrict__ b1v) {
    __shared__ float sa[660];
    __shared__ float red[512];
    int tid = threadIdx.x;
    int ht = blockIdx.x, ch = blockIdx.y, b = blockIdx.z;
    int h0 = ht * 8;
    float m  = g_ms1[(b * 8 + (ch >> 6)) * 2 + 0];
    float rs = g_ms1[(b * 8 + (ch >> 6)) * 2 + 1];
    float sc = s1v[ch], bi = b1v[ch];
    for (int idx = tid; idx < 660; idx += 256) {
        int r = idx / 66, i = idx % 66;
        int hh = h0 - 1 + r, ww = i - 1;
        float v = 0.f;
        if (hh >= 0 && hh < 64 && ww >= 0 && ww < 64) {
            float t = (g_h1[((b * NHC + ch) * 64 + hh) * 64 + ww] - m) * rs * sc + bi;
            v = silu_f(t);
        }
        sa[idx] = v;
    }
    __syncthreads();
    float wd[9];
#pragma unroll
    for (int j = 0; j < 9; j++) wd[j] = w_dw[ch * 9 + j];
    float s1 = 0.f, s2 = 0.f;
#pragma unroll
    for (int oo = 0; oo < 2; oo++) {
        int o = tid + oo * 256;
        int r = o >> 6, w = o & 63;
        float a = 0.f;
#pragma unroll
        for (int dr = 0; dr < 3; dr++)
#pragma unroll
            for (int dt = 0; dt < 3; dt++)
                a += sa[(r + dr) * 66 + w + dt] * wd[dr * 3 + dt];
        g_h2[((b * NHC + ch) * 64 + h0 + r) * 64 + w] = a;
        s1 += a; s2 += a * a;
    }
    red[tid] = s1; red[256 + tid] = s2;
    __syncthreads();
    for (int st = 128; st > 0; st >>= 1) {
        if (tid < st) { red[tid] += red[tid + st]; red[256 + tid] += red[256 + tid + st]; }
        __syncthreads();
    }
    if (tid == 0) {
        int slot = b * 8 + (ch >> 6);
        int entry = (ch & 63) * 8 + ht;
        g_part2[(slot * 512 + entry) * 2 + 0] = red[0];
        g_part2[(slot * 512 + entry) * 2 + 1] = red[256];
    }
}

// ---------------- K8: pw2 1x1 stride-2, 512->128 (normalize h2 on load) -----
// grid (16 px-tiles, 16 b); block 256; tile 64px x 128co, 4x8 per thread
__global__ __launch_bounds__(256) void k_pw2(const float* __restrict__ w_pw2,
                                             const float* __restrict__ s2v,
                                             const float* __restrict__ b2v) {
    __shared__ float sA[2048], sW[4096], red[512];
    int tid = threadIdx.x;
    int pt = blockIdx.x, b = blockIdx.y;
    int pg = tid & 15, og = tid >> 4;
    float acc[32];
#pragma unroll
    for (int i = 0; i < 32; i++) acc[i] = 0.f;

    for (int c0 = 0; c0 < 512; c0 += 32) {
        __syncthreads();
        for (int idx = tid; idx < 2048; idx += 256) {
            int kc = idx >> 6, p = idx & 63;
            int hc = c0 + kc;
            int pi = pt * 64 + p;
            int ii = pi >> 5, jj = pi & 31;
            float v = g_h2[((b * NHC + hc) * 64 + 2 * ii) * 64 + 2 * jj];
            float m  = g_ms2[(b * 8 + (hc >> 6)) * 2 + 0];
            float rr = g_ms2[(b * 8 + (hc >> 6)) * 2 + 1];
            float t = (v - m) * rr * s2v[hc] + b2v[hc];
            sA[idx] = silu_f(t);
        }
        for (int idx = tid; idx < 4096; idx += 256) {
            int kc = idx >> 7, co = idx & 127;
            sW[idx] = w_pw2[co * NHC + c0 + kc];
        }
        __syncthreads();
        for (int kc = 0; kc < 32; kc++) {
            float a0 = sA[kc * 64 + 4 * pg + 0];
            float a1 = sA[kc * 64 + 4 * pg + 1];
            float a2 = sA[kc * 64 + 4 * pg + 2];
            float a3 = sA[kc * 64 + 4 * pg + 3];
#pragma unroll
            for (int l = 0; l < 8; l++) {
                float wv = sW[kc * 128 + 8 * og + l];
                acc[0 * 8 + l] += a0 * wv;
                acc[1 * 8 + l] += a1 * wv;
                acc[2 * 8 + l] += a2 * wv;
                acc[3 * 8 + l] += a3 * wv;
            }
        }
    }
    // stats: group of 16 co == 32-thread segment (tid>>5)
    float s1 = 0.f, s2 = 0.f;
#pragma unroll
    for (int i = 0; i < 32; i++) { s1 += acc[i]; s2 += acc[i] * acc[i]; }
    red[tid] = s1; red[256 + tid] = s2;
    __syncthreads();
    if ((tid & 31) == 0) {
        float a = 0.f, bq = 0.f;
        for (int i = 0; i < 32; i++) { a += red[tid + i]; bq += red[256 + tid + i]; }
        int g = tid >> 5;
        g_part3[((b * 8 + g) * 16 + pt) * 2 + 0] = a;
        g_part3[((b * 8 + g) * 16 + pt) * 2 + 1] = bq;
    }
    // write raw h3
#pragma unroll
    for (int k = 0; k < 4; k++) {
        int pi = pt * 64 + 4 * pg + k;
        int ii = pi >> 5, jj = pi & 31;
#pragma unroll
        for (int l = 0; l < 8; l++) {
            int co = 8 * og + l;
            g_h3[((b * NC + co) << 10) + (ii << 5) + jj] = acc[k * 8 + l];
        }
    }
}

// ---------------- K10: final GN + SiLU -> output -----------------------------
__global__ void k_out(float* __restrict__ out,
                      const float* __restrict__ s3v, const float* __restrict__ b3v) {
    int idx = blockIdx.x * 256 + threadIdx.x;   // 2097152
    int co = (idx >> 10) & 127, b = idx >> 17;
    int g = co >> 4;
    float m  = g_ms3[(b * 8 + g) * 2 + 0];
    float rs = g_ms3[(b * 8 + g) * 2 + 1];
    float t = (g_h3[idx] - m) * rs * s3v[co] + b3v[co];
    out[idx] = silu_f(t);
}

// ---------------- launch ----------------------------------------------------
extern "C" void kernel_launch(void* const* d_in, const int* in_sizes, int n_in,
                              void* d_out, int out_size) {
    const float* x      = (const float*)d_in[0];
    const float* w_exp  = (const float*)d_in[1];
    const float* gs_e   = (const float*)d_in[2];
    const float* gb_e   = (const float*)d_in[3];
    const float* w1     = (const float*)d_in[4];
    const float* b1     = (const float*)d_in[5];
    const float* w2     = (const float*)d_in[6];
    const float* b2     = (const float*)d_in[7];
    const float* w_pw1  = (const float*)d_in[8];
    const float* gn1_s  = (const float*)d_in[9];
    const float* gn1_b  = (const float*)d_in[10];
    const float* w_dw   = (const float*)d_in[11];
    const float* gn2_s  = (const float*)d_in[12];
    const float* gn2_b  = (const float*)d_in[13];
    const float* w_pw2  = (const float*)d_in[14];
    const float* gn3_s  = (const float*)d_in[15];
    const float* gn3_b  = (const float*)d_in[16];
    float* out = (float*)d_out;

    k_router<<<1, 1024>>>(w1, b1, w2, b2);
    k_expert<<<dim3(16, 32, 16), 256>>>(x, w_exp);
    k_finalize<<<4, 256>>>(0);
    k_combine<<<32768, 256>>>(x, gs_e, gb_e);
    k_pw1<<<dim3(8, 64, 16), 256>>>(w_pw1);
    k_finalize<<<4, 256>>>(1);
    k_dw<<<dim3(8, 512, 16), 256>>>(w_dw, gn1_s, gn1_b);
    k_finalize<<<4, 256>>>(2);
    k_pw2<<<dim3(16, 16), 256>>>(w_pw2, gn2_s, gn2_b);
    k_finalize<<<4, 256>>>(3);
    k_out<<<8192, 256>>>(out, gn3_s, gn3_b);
}

// round 2
// speedup vs baseline: 2.0626x; 2.0626x over previous
#include <cuda_runtime.h>
#include <math.h>

// ---------------- problem constants ----------------
#define NB   16
#define NC   128
#define NH   64
#define NW   64
#define NE   8
#define NHC  512
#define HWSZ 4096

// ---------------- scratch ----------------
__device__ float g_z[67108864];     // [E][B][C][H][W]
__device__ float g_comb[8388608];
__device__ float g_h1[33554432];
__device__ float g_h2[33554432];
__device__ float g_h3[2097152];
__device__ float g_wts[128];
__device__ float g_xr[8388608];     // tf32-rounded x
__device__ float g_wr[1179648];     // tf32-rounded w_exp
__device__ float g_part_exp[1024 * 32 * 2];
__device__ float g_ms_exp[1024 * 2];
__device__ float g_part1[128 * 64 * 2];
__device__ float g_ms1[128 * 2];
__device__ float g_part2[128 * 512 * 2];
__device__ float g_ms2[128 * 2];
__device__ float g_part3[128 * 16 * 2];
__device__ float g_ms3[128 * 2];

__device__ __forceinline__ float silu_f(float x) {
    return x / (1.0f + expf(-x));
}

// ---------------- tf32 pre-round ----------------
__global__ void k_round(const float* __restrict__ src, float* __restrict__ dst, int n) {
    int i = blockIdx.x * 256 + threadIdx.x;
    if (i < n) {
        unsigned u;
        asm("cvt.rna.tf32.f32 %0, %1;" : "=r"(u) : "f"(src[i]));
        dst[i] = __uint_as_float(u);
    }
}

// ---------------- router ----------------
__global__ void k_router(const float* __restrict__ w1, const float* __restrict__ b1,
                         const float* __restrict__ w2, const float* __restrict__ b2) {
    __shared__ float feats[16 * 32];
    __shared__ float hid[16 * 64];
    __shared__ float lg[16 * 8];
    int tid = threadIdx.x;
    if (tid < 512) {
        int p = tid >> 5, f = tid & 31;
        int py = p >> 2, px = p & 3;
        int k = f & 7, kind = f >> 3;
        float freq = exp2f((float)k) * 3.14159265358979323846f;
        float cy = (py + 0.5f) * 0.25f;
        float cx = (px + 0.5f) * 0.25f;
        float v;
        if (kind == 0)      v = sinf(cy * freq);
        else if (kind == 1) v = cosf(cy * freq);
        else if (kind == 2) v = sinf(cx * freq);
        else                v = cosf(cx * freq);
        feats[p * 32 + f] = v;
    }
    __syncthreads();
    {
        int p = tid >> 6, hh = tid & 63;
        float a = b1[hh];
        for (int f = 0; f < 32; f++) a += feats[p * 32 + f] * w1[f * 64 + hh];
        hid[p * 64 + hh] = silu_f(a);
    }
    __syncthreads();
    if (tid < 128) {
        int p = tid >> 3, e = tid & 7;
        float a = b2[e];
        for (int hh = 0; hh < 64; hh++) a += hid[p * 64 + hh] * w2[hh * 8 + e];
        lg[p * 8 + e] = a;
    }
    __syncthreads();
    if (tid < 16) {
        float mx = -1e30f;
        for (int e = 0; e < 8; e++) mx = fmaxf(mx, lg[tid * 8 + e]);
        float ex[8], s = 0.f;
        for (int e = 0; e < 8; e++) { ex[e] = expf(lg[tid * 8 + e] - mx); s += ex[e]; }
        float inv = 1.0f / s;
        for (int e = 0; e < 8; e++) g_wts[tid * 8 + e] = ex[e] * inv;
    }
}

// ---------------- expert conv via mma.sync tf32 ----------------
// Block: 256 thr (8 warps), tile 64 oc x 128 px (2 rows x 64 w).
// grid (octile=2, hb=32, e*16+b=128). K = 128 c (chunks of 8) x 9 taps.
// smem float offsets:
#define XO0 0
#define WO0 2376
#define XO1 7569
#define WO1 9945
#define REDO 15138
#define SMEMF 15160

__device__ __forceinline__ void cp4(unsigned s, const void* g, int sz) {
    asm volatile("cp.async.ca.shared.global [%0], [%1], 4, %2;\n"
                 :: "r"(s), "l"(g), "r"(sz) : "memory");
}
__device__ __forceinline__ void cp_commit() {
    asm volatile("cp.async.commit_group;\n" ::: "memory");
}
__device__ __forceinline__ void cp_wait1() {
    asm volatile("cp.async.wait_group 1;\n" ::: "memory");
}
__device__ __forceinline__ void mma8(float* c, unsigned a0, unsigned a1, unsigned a2,
                                     unsigned a3, unsigned b0, unsigned b1) {
    asm volatile("mma.sync.aligned.m16n8k8.row.col.f32.tf32.tf32.f32 "
                 "{%0,%1,%2,%3}, {%4,%5,%6,%7}, {%8,%9}, {%0,%1,%2,%3};"
                 : "+f"(c[0]), "+f"(c[1]), "+f"(c[2]), "+f"(c[3])
                 : "r"(a0), "r"(a1), "r"(a2), "r"(a3), "r"(b0), "r"(b1));
}

extern __shared__ float smem_all[];

__global__ __launch_bounds__(256) void k_expert_mma() {
    int tid = threadIdx.x;
    int wid = tid >> 5, lane = tid & 31;
    int q = lane >> 2, r = lane & 3;
    int ocw = wid >> 1, ph = wid & 1;
    int octile = blockIdx.x, hb = blockIdx.y;
    int b = blockIdx.z & 15, e = blockIdx.z >> 4;

    unsigned smem_u = (unsigned)__cvta_generic_to_shared(smem_all);

    float acc[32];
#pragma unroll
    for (int i = 0; i < 32; i++) acc[i] = 0.f;

    // staging lambda: chunk -> buffer bf
    auto stage = [&](int chunk, int bf) {
        int c0 = chunk * 8;
        unsigned sxa = smem_u + 4u * (bf ? XO1 : XO0);
        unsigned swa = smem_u + 4u * (bf ? WO1 : WO0);
        // X: [4 rows][66 wl][8 c], pitch 9
        for (int idx = tid; idx < 2112; idx += 256) {
            int c = idx / 264, rem = idx - c * 264;
            int row = rem / 66, wl = rem - row * 66;
            int ih = 2 * hb - 1 + row, iw = wl - 1;
            bool v = ((unsigned)ih < 64u) && ((unsigned)iw < 64u);
            int ihc = v ? ih : 0, iwc = v ? iw : 0;
            const float* g = g_xr + (((b * 128 + c0 + c) * 64 + ihc) * 64 + iwc);
            cp4(sxa + 4u * (row * 594 + wl * 9 + c), g, v ? 4 : 0);
        }
        // W: [9 taps pitch 577][64 oc pitch 9][8 c]
        for (int idx = tid; idx < 4608; idx += 256) {
            int ocl = idx / 72, u = idx - ocl * 72;
            int c = u / 9, tap = u - c * 9;
            const float* g = g_wr + ((size_t)((e * 128 + octile * 64 + ocl) * 128 + c0 + c)) * 9 + tap;
            cp4(swa + 4u * (tap * 577 + ocl * 9 + c), g, 4);
        }
    };

    stage(0, 0); cp_commit();
    stage(1, 1); cp_commit();

    for (int k = 0; k < 16; k++) {
        cp_wait1();
        __syncthreads();
        int bf = k & 1;
        const float* sX = smem_all + (bf ? XO1 : XO0);
        const float* sW = smem_all + (bf ? WO1 : WO0);
#pragma unroll
        for (int tap = 0; tap < 9; tap++) {
            int dy = tap / 3, dx = tap - dy * 3;
            const float* wp = sW + tap * 577 + (ocw * 16 + q) * 9 + r;
            unsigned a0 = __float_as_uint(wp[0]);
            unsigned a1 = __float_as_uint(wp[72]);
            unsigned a2 = __float_as_uint(wp[4]);
            unsigned a3 = __float_as_uint(wp[76]);
            const float* xp = sX + (ph + dy) * 594 + (q + dx) * 9 + r;
#pragma unroll
            for (int nt = 0; nt < 8; nt++) {
                unsigned b0 = __float_as_uint(xp[nt * 72]);
                unsigned b1 = __float_as_uint(xp[nt * 72 + 4]);
                mma8(acc + nt * 4, a0, a1, a2, a3, b0, b1);
            }
        }
        __syncthreads();
        if (k + 2 < 16) stage(k + 2, bf);
        cp_commit();
    }

    // ---- group stats: warp covers 16 consecutive oc (one group slice) ----
    float s1 = 0.f, s2 = 0.f;
#pragma unroll
    for (int i = 0; i < 32; i++) { s1 += acc[i]; s2 += acc[i] * acc[i]; }
#pragma unroll
    for (int off = 16; off > 0; off >>= 1) {
        s1 += __shfl_xor_sync(0xffffffffu, s1, off);
        s2 += __shfl_xor_sync(0xffffffffu, s2, off);
    }
    float* red = smem_all + REDO;
    if (lane == 0) { red[wid] = s1; red[8 + wid] = s2; }

    // ---- stage outputs into smem [64 oc][128 px], pitch 129 ----
    float* stg = smem_all;
#pragma unroll
    for (int nt = 0; nt < 8; nt++) {
#pragma unroll
        for (int j = 0; j < 4; j++) {
            int ocl = ocw * 16 + q + 8 * (j >> 1);
            int w = nt * 8 + 2 * r + (j & 1);
            stg[ocl * 129 + ph * 64 + w] = acc[nt * 4 + j];
        }
    }
    __syncthreads();
    if (tid < 4) {
        float a = red[2 * tid] + red[2 * tid + 1];
        float bq = red[8 + 2 * tid] + red[8 + 2 * tid + 1];
        int g = octile * 4 + tid;
        int slot = (e * NB + b) * 8 + g;
        g_part_exp[(slot * 32 + hb) * 2 + 0] = a;
        g_part_exp[(slot * 32 + hb) * 2 + 1] = bq;
    }
    for (int idx = tid; idx < 8192; idx += 256) {
        int ocl = idx >> 7, p = idx & 127;
        int h = 2 * hb + (p >> 6), w = p & 63;
        g_z[((size_t)((e * NB + b) * NC + octile * 64 + ocl)) * HWSZ + h * 64 + w] =
            stg[ocl * 129 + p];
    }
}

// ---------------- finalize stats ----------------
__global__ void k_finalize(int which) {
    const float* part; float* ms; int nper, nslots; float invN;
    if (which == 0)      { part = g_part_exp; ms = g_ms_exp; nper = 32;  nslots = 1024; invN = 1.0f / 65536.0f; }
    else if (which == 1) { part = g_part1;    ms = g_ms1;    nper = 64;  nslots = 128;  invN = 1.0f / 262144.0f; }
    else if (which == 2) { part = g_part2;    ms = g_ms2;    nper = 512; nslots = 128;  invN = 1.0f / 262144.0f; }
    else                 { part = g_part3;    ms = g_ms3;    nper = 16;  nslots = 128;  invN = 1.0f / 16384.0f; }
    int s = blockIdx.x * blockDim.x + threadIdx.x;
    if (s >= nslots) return;
    float s1 = 0.f, s2 = 0.f;
    for (int i = 0; i < nper; i++) {
        s1 += part[(s * nper + i) * 2 + 0];
        s2 += part[(s * nper + i) * 2 + 1];
    }
    float m = s1 * invN;
    float v = s2 * invN - m * m;
    ms[s * 2 + 0] = m;
    ms[s * 2 + 1] = rsqrtf(v + 1e-5f);
}

// ---------------- combine ----------------
__global__ __launch_bounds__(256) void k_combine(const float* __restrict__ x,
                                                 const float* __restrict__ gs,
                                                 const float* __restrict__ gb) {
    int idx = blockIdx.x * 256 + threadIdx.x;
    int w = idx & 63, h = (idx >> 6) & 63, c = (idx >> 12) & 127, b = idx >> 19;
    int patch = ((h >> 4) << 2) + (w >> 4);
    int g = c >> 4;
    float a = x[idx];
    int hw = idx & 4095;
#pragma unroll
    for (int e = 0; e < 8; e++) {
        float zv = g_z[((size_t)((e * NB + b) * NC + c)) * HWSZ + hw];
        float m  = g_ms_exp[(((e * NB + b) * 8) + g) * 2 + 0];
        float rs = g_ms_exp[(((e * NB + b) * 8) + g) * 2 + 1];
        float t = (zv - m) * rs * gs[e * NC + c] + gb[e * NC + c];
        a += g_wts[patch * 8 + e] * silu_f(t);
    }
    g_comb[idx] = a;
}

// ---------------- pw1 ----------------
__global__ __launch_bounds__(256) void k_pw1(const float* __restrict__ w_pw1) {
    __shared__ float sA[4096], sW[4096], red[512];
    int tid = threadIdx.x;
    int g = blockIdx.x, pt = blockIdx.y, b = blockIdx.z;
    int hc0 = g * 64, px0 = pt * 64;
    int pg = tid & 15, og = tid >> 4;
    float acc[16];
#pragma unroll
    for (int i = 0; i < 16; i++) acc[i] = 0.f;

    for (int c0 = 0; c0 < 128; c0 += 64) {
        __syncthreads();
        for (int idx = tid; idx < 4096; idx += 256) {
            int cc = idx >> 6, p = idx & 63;
            sA[idx] = g_comb[(b * NC + c0 + cc) * HWSZ + px0 + p];
        }
        for (int idx = tid; idx < 4096; idx += 256) {
            int hc = idx >> 6, cc = idx & 63;
            sW[idx] = w_pw1[(hc0 + hc) * NC + c0 + cc];
        }
        __syncthreads();
        for (int cc = 0; cc < 64; cc++) {
            float a0 = sA[cc * 64 + 4 * pg + 0];
            float a1 = sA[cc * 64 + 4 * pg + 1];
            float a2 = sA[cc * 64 + 4 * pg + 2];
            float a3 = sA[cc * 64 + 4 * pg + 3];
#pragma unroll
            for (int l = 0; l < 4; l++) {
                float wv = sW[(4 * og + l) * 64 + cc];
                acc[0 * 4 + l] += a0 * wv;
                acc[1 * 4 + l] += a1 * wv;
                acc[2 * 4 + l] += a2 * wv;
                acc[3 * 4 + l] += a3 * wv;
            }
        }
    }
    float s1 = 0.f, s2 = 0.f;
#pragma unroll
    for (int i = 0; i < 16; i++) { s1 += acc[i]; s2 += acc[i] * acc[i]; }
    red[tid] = s1; red[256 + tid] = s2;
    __syncthreads();
    for (int st = 128; st > 0; st >>= 1) {
        if (tid < st) { red[tid] += red[tid + st]; red[256 + tid] += red[256 + tid + st]; }
        __syncthreads();
    }
    if (tid == 0) {
        g_part1[((b * 8 + g) * 64 + pt) * 2 + 0] = red[0];
        g_part1[((b * 8 + g) * 64 + pt) * 2 + 1] = red[256];
    }
    __syncthreads();
#pragma unroll
    for (int k = 0; k < 4; k++)
#pragma unroll
        for (int l = 0; l < 4; l++)
            sA[(4 * og + l) * 64 + 4 * pg + k] = acc[k * 4 + l];
    __syncthreads();
    for (int idx = tid; idx < 4096; idx += 256) {
        int hcl = idx >> 6, p = idx & 63;
        g_h1[(size_t)(b * NHC + hc0 + hcl) * HWSZ + px0 + p] = sA[idx];
    }
}

// ---------------- dw ----------------
__global__ __launch_bounds__(256) void k_dw(const float* __restrict__ w_dw,
                                            const float* __restrict__ s1v,
                                            const float* __restrict__ b1v) {
    __shared__ float sa[660];
    __shared__ float red[512];
    int tid = threadIdx.x;
    int ht = blockIdx.x, ch = blockIdx.y, b = blockIdx.z;
    int h0 = ht * 8;
    float m  = g_ms1[(b * 8 + (ch >> 6)) * 2 + 0];
    float rs = g_ms1[(b * 8 + (ch >> 6)) * 2 + 1];
    float sc = s1v[ch], bi = b1v[ch];
    for (int idx = tid; idx < 660; idx += 256) {
        int r = idx / 66, i = idx % 66;
        int hh = h0 - 1 + r, ww = i - 1;
        float v = 0.f;
        if (hh >= 0 && hh < 64 && ww >= 0 && ww < 64) {
            float t = (g_h1[((size_t)(b * NHC + ch) * 64 + hh) * 64 + ww] - m) * rs * sc + bi;
            v = silu_f(t);
        }
        sa[idx] = v;
    }
    __syncthreads();
    float wd[9];
#pragma unroll
    for (int j = 0; j < 9; j++) wd[j] = w_dw[ch * 9 + j];
    float s1 = 0.f, s2 = 0.f;
#pragma unroll
    for (int oo = 0; oo < 2; oo++) {
        int o = tid + oo * 256;
        int r = o >> 6, w = o & 63;
        float a = 0.f;
#pragma unroll
        for (int dr = 0; dr < 3; dr++)
#pragma unroll
            for (int dt = 0; dt < 3; dt++)
                a += sa[(r + dr) * 66 + w + dt] * wd[dr * 3 + dt];
        g_h2[((size_t)(b * NHC + ch) * 64 + h0 + r) * 64 + w] = a;
        s1 += a; s2 += a * a;
    }
    red[tid] = s1; red[256 + tid] = s2;
    __syncthreads();
    for (int st = 128; st > 0; st >>= 1) {
        if (tid < st) { red[tid] += red[tid + st]; red[256 + tid] += red[256 + tid + st]; }
        __syncthreads();
    }
    if (tid == 0) {
        int slot = b * 8 + (ch >> 6);
        int entry = (ch & 63) * 8 + ht;
        g_part2[(slot * 512 + entry) * 2 + 0] = red[0];
        g_part2[(slot * 512 + entry) * 2 + 1] = red[256];
    }
}

// ---------------- pw2 ----------------
__global__ __launch_bounds__(256) void k_pw2(const float* __restrict__ w_pw2,
                                             const float* __restrict__ s2v,
                                             const float* __restrict__ b2v) {
    __shared__ float sA[2048], sW[4096], red[512];
    int tid = threadIdx.x;
    int pt = blockIdx.x, b = blockIdx.y;
    int pg = tid & 15, og = tid >> 4;
    float acc[32];
#pragma unroll
    for (int i = 0; i < 32; i++) acc[i] = 0.f;

    for (int c0 = 0; c0 < 512; c0 += 32) {
        __syncthreads();
        for (int idx = tid; idx < 2048; idx += 256) {
            int kc = idx >> 6, p = idx & 63;
            int hc = c0 + kc;
            int pi = pt * 64 + p;
            int ii = pi >> 5, jj = pi & 31;
            float v = g_h2[((size_t)(b * NHC + hc) * 64 + 2 * ii) * 64 + 2 * jj];
            float m  = g_ms2[(b * 8 + (hc >> 6)) * 2 + 0];
            float rr = g_ms2[(b * 8 + (hc >> 6)) * 2 + 1];
            float t = (v - m) * rr * s2v[hc] + b2v[hc];
            sA[idx] = silu_f(t);
        }
        for (int idx = tid; idx < 4096; idx += 256) {
            int kc = idx >> 7, co = idx & 127;
            sW[idx] = w_pw2[co * NHC + c0 + kc];
        }
        __syncthreads();
        for (int kc = 0; kc < 32; kc++) {
            float a0 = sA[kc * 64 + 4 * pg + 0];
            float a1 = sA[kc * 64 + 4 * pg + 1];
            float a2 = sA[kc * 64 + 4 * pg + 2];
            float a3 = sA[kc * 64 + 4 * pg + 3];
#pragma unroll
            for (int l = 0; l < 8; l++) {
                float wv = sW[kc * 128 + 8 * og + l];
                acc[0 * 8 + l] += a0 * wv;
                acc[1 * 8 + l] += a1 * wv;
                acc[2 * 8 + l] += a2 * wv;
                acc[3 * 8 + l] += a3 * wv;
            }
        }
    }
    float s1 = 0.f, s2 = 0.f;
#pragma unroll
    for (int i = 0; i < 32; i++) { s1 += acc[i]; s2 += acc[i] * acc[i]; }
    red[tid] = s1; red[256 + tid] = s2;
    __syncthreads();
    if ((tid & 31) == 0) {
        float a = 0.f, bq = 0.f;
        for (int i = 0; i < 32; i++) { a += red[tid + i]; bq += red[256 + tid + i]; }
        int g = tid >> 5;
        g_part3[((b * 8 + g) * 16 + pt) * 2 + 0] = a;
        g_part3[((b * 8 + g) * 16 + pt) * 2 + 1] = bq;
    }
#pragma unroll
    for (int k = 0; k < 4; k++) {
        int pi = pt * 64 + 4 * pg + k;
        int ii = pi >> 5, jj = pi & 31;
#pragma unroll
        for (int l = 0; l < 8; l++) {
            int co = 8 * og + l;
            g_h3[((b * NC + co) << 10) + (ii << 5) + jj] = acc[k * 8 + l];
        }
    }
}

// ---------------- final ----------------
__global__ void k_out(float* __restrict__ out,
                      const float* __restrict__ s3v, const float* __restrict__ b3v) {
    int idx = blockIdx.x * 256 + threadIdx.x;
    int co = (idx >> 10) & 127, b = idx >> 17;
    int g = co >> 4;
    float m  = g_ms3[(b * 8 + g) * 2 + 0];
    float rs = g_ms3[(b * 8 + g) * 2 + 1];
    float t = (g_h3[idx] - m) * rs * s3v[co] + b3v[co];
    out[idx] = silu_f(t);
}

// ---------------- launch ----------------
extern "C" void kernel_launch(void* const* d_in, const int* in_sizes, int n_in,
                              void* d_out, int out_size) {
    const float* x      = (const float*)d_in[0];
    const float* w_exp  = (const float*)d_in[1];
    const float* gs_e   = (const float*)d_in[2];
    const float* gb_e   = (const float*)d_in[3];
    const float* w1     = (const float*)d_in[4];
    const float* b1     = (const float*)d_in[5];
    const float* w2     = (const float*)d_in[6];
    const float* b2     = (const float*)d_in[7];
    const float* w_pw1  = (const float*)d_in[8];
    const float* gn1_s  = (const float*)d_in[9];
    const float* gn1_b  = (const float*)d_in[10];
    const float* w_dw   = (const float*)d_in[11];
    const float* gn2_s  = (const float*)d_in[12];
    const float* gn2_b  = (const float*)d_in[13];
    const float* w_pw2  = (const float*)d_in[14];
    const float* gn3_s  = (const float*)d_in[15];
    const float* gn3_b  = (const float*)d_in[16];
    float* out = (float*)d_out;

    static bool attr_done = false;
    if (!attr_done) {
        cudaFuncSetAttribute(k_expert_mma, cudaFuncAttributeMaxDynamicSharedMemorySize,
                             SMEMF * 4);
        attr_done = true;
    }

    float* xr; cudaGetSymbolAddress((void**)&xr, g_xr);
    float* wr; cudaGetSymbolAddress((void**)&wr, g_wr);

    k_round<<<32768, 256>>>(x, xr, 8388608);
    k_round<<<4608, 256>>>(w_exp, wr, 1179648);
    k_router<<<1, 1024>>>(w1, b1, w2, b2);
    k_expert_mma<<<dim3(2, 32, 128), 256, SMEMF * 4>>>();
    k_finalize<<<4, 256>>>(0);
    k_combine<<<32768, 256>>>(x, gs_e, gb_e);
    k_pw1<<<dim3(8, 64, 16), 256>>>(w_pw1);
    k_finalize<<<4, 256>>>(1);
    k_dw<<<dim3(8, 512, 16), 256>>>(w_dw, gn1_s, gn1_b);
    k_finalize<<<4, 256>>>(2);
    k_pw2<<<dim3(16, 16), 256>>>(w_pw2, gn2_s, gn2_b);
    k_finalize<<<4, 256>>>(3);
    k_out<<<8192, 256>>>(out, gn3_s, gn3_b);
}

// round 4
// speedup vs baseline: 4.1691x; 2.0213x over previous
#include <cuda_runtime.h>
#include <math.h>

// ---------------- problem constants ----------------
#define NB   16
#define NC   128
#define NHC  512
#define HWSZ 4096

// ---------------- scratch ----------------
__device__ float g_z[67108864];      // [E*B][C][HW] expert conv raw
__device__ float g_combp[8388608];   // [B][chunk16][px4096][cp8] tf32
__device__ float g_h1[33554432];
__device__ float g_h2[33554432];
__device__ float g_h3[2097152];
__device__ float g_wts[128];
__device__ float g_xr[8388608];      // [B][chunk16][h][w][cp8] tf32
__device__ float g_wr[1179648];      // [E][chunk16][tap9][oc128][cp8] tf32
__device__ float g_w1r[65536];       // [ht4][chunk16][hcl128][cp8] tf32
__device__ float g_part_exp[1024 * 32 * 2];
__device__ float g_ms_exp[1024 * 2];
__device__ float g_part1[128 * 32 * 2];
__device__ float g_ms1[128 * 2];
__device__ float g_part2[128 * 512 * 2];
__device__ float g_ms2[128 * 2];
__device__ float g_part3[128 * 16 * 2];
__device__ float g_ms3[128 * 2];

__device__ __forceinline__ float silu_f(float x) {
    return x / (1.0f + expf(-x));
}
__device__ __forceinline__ float tf32r(float x) {
    unsigned u;
    asm("cvt.rna.tf32.f32 %0, %1;" : "=r"(u) : "f"(x));
    return __uint_as_float(u);
}
__device__ __forceinline__ void cp16(unsigned s, const void* g, int sz) {
    asm volatile("cp.async.cg.shared.global [%0], [%1], 16, %2;\n"
                 :: "r"(s), "l"(g), "r"(sz) : "memory");
}
__device__ __forceinline__ void cp_commit() {
    asm volatile("cp.async.commit_group;\n" ::: "memory");
}
__device__ __forceinline__ void cp_wait1() {
    asm volatile("cp.async.wait_group 1;\n" ::: "memory");
}
__device__ __forceinline__ void mma8(float* c, float a0, float a1, float a2, float a3,
                                     float b0, float b1) {
    asm volatile("mma.sync.aligned.m16n8k8.row.col.f32.tf32.tf32.f32 "
                 "{%0,%1,%2,%3}, {%4,%5,%6,%7}, {%8,%9}, {%0,%1,%2,%3};"
                 : "+f"(c[0]), "+f"(c[1]), "+f"(c[2]), "+f"(c[3])
                 : "r"(__float_as_uint(a0)), "r"(__float_as_uint(a1)),
                   "r"(__float_as_uint(a2)), "r"(__float_as_uint(a3)),
                   "r"(__float_as_uint(b0)), "r"(__float_as_uint(b1)));
}

// ---------------- transforms (tf32-round + permute to staging layouts) ------
// cp = (c&3)*2 + (c>>2);  inverse: c = (cp>>1) + (cp&1)*4
__global__ void k_xform_x(const float* __restrict__ x) {
    int idx = blockIdx.x * 256 + threadIdx.x;   // 1048576
    int w = idx & 63, h = (idx >> 6) & 63, chunk = (idx >> 12) & 15, b = idx >> 16;
    float o[8];
#pragma unroll
    for (int j = 0; j < 8; j++) {
        int c = chunk * 8 + (j >> 1) + (j & 1) * 4;
        o[j] = tf32r(x[((b * 128 + c) << 12) + (h << 6) + w]);
    }
    float4* dst = (float4*)(g_xr + (size_t)idx * 8);
    dst[0] = make_float4(o[0], o[1], o[2], o[3]);
    dst[1] = make_float4(o[4], o[5], o[6], o[7]);
}

__global__ void k_xform_w(const float* __restrict__ w_exp) {
    int idx = blockIdx.x * 256 + threadIdx.x;   // 1179648
    int cp = idx & 7, ocl = (idx >> 3) & 127;
    int t2 = idx >> 10;
    int tap = t2 % 9, ec = t2 / 9;
    int chunk = ec & 15, e = ec >> 4;
    int c = chunk * 8 + (cp >> 1) + (cp & 1) * 4;
    g_wr[idx] = tf32r(w_exp[((e * 128 + ocl) * 128 + c) * 9 + tap]);
}

__global__ void k_xform_w1(const float* __restrict__ w_pw1) {
    int idx = blockIdx.x * 256 + threadIdx.x;   // 65536
    int cp = idx & 7, hcl = (idx >> 3) & 127, chunk = (idx >> 10) & 15, ht = idx >> 14;
    int c = chunk * 8 + (cp >> 1) + (cp & 1) * 4;
    g_w1r[idx] = tf32r(w_pw1[(ht * 128 + hcl) * 128 + c]);
}

// ---------------- router ----------------
__global__ void k_router(const float* __restrict__ w1, const float* __restrict__ b1,
                         const float* __restrict__ w2, const float* __restrict__ b2) {
    __shared__ float feats[16 * 32];
    __shared__ float hid[16 * 64];
    __shared__ float lg[16 * 8];
    int tid = threadIdx.x;
    if (tid < 512) {
        int p = tid >> 5, f = tid & 31;
        int py = p >> 2, px = p & 3;
        int k = f & 7, kind = f >> 3;
        float freq = exp2f((float)k) * 3.14159265358979323846f;
        float cy = (py + 0.5f) * 0.25f;
        float cx = (px + 0.5f) * 0.25f;
        float v;
        if (kind == 0)      v = sinf(cy * freq);
        else if (kind == 1) v = cosf(cy * freq);
        else if (kind == 2) v = sinf(cx * freq);
        else                v = cosf(cx * freq);
        feats[p * 32 + f] = v;
    }
    __syncthreads();
    {
        int p = tid >> 6, hh = tid & 63;
        float a = b1[hh];
        for (int f = 0; f < 32; f++) a += feats[p * 32 + f] * w1[f * 64 + hh];
        hid[p * 64 + hh] = silu_f(a);
    }
    __syncthreads();
    if (tid < 128) {
        int p = tid >> 3, e = tid & 7;
        float a = b2[e];
        for (int hh = 0; hh < 64; hh++) a += hid[p * 64 + hh] * w2[hh * 8 + e];
        lg[p * 8 + e] = a;
    }
    __syncthreads();
    if (tid < 16) {
        float mx = -1e30f;
        for (int e = 0; e < 8; e++) mx = fmaxf(mx, lg[tid * 8 + e]);
        float ex[8], s = 0.f;
        for (int e = 0; e < 8; e++) { ex[e] = expf(lg[tid * 8 + e] - mx); s += ex[e]; }
        float inv = 1.0f / s;
        for (int e = 0; e < 8; e++) g_wts[tid * 8 + e] = ex[e] * inv;
    }
}

// ---------------- expert conv: tf32 mma, block 128oc x 128px ----------------
// 8 warps = ocw(4: 32oc) x ph(2: row). grid (hb=32, e*16+b=128).
#define XO0 0
#define WO0 2112
#define XO1 11328
#define WO1 13440
#define REDE 22656
#define EXPF 22688

extern __shared__ float smem_all[];

__global__ __launch_bounds__(256, 2) void k_expert_mma() {
    int tid = threadIdx.x;
    int wid = tid >> 5, lane = tid & 31;
    int q = lane >> 2, r = lane & 3;
    int ocw = wid >> 1, ph = wid & 1;
    int hb = blockIdx.x;
    int b = blockIdx.y & 15, e = blockIdx.y >> 4;
    unsigned smem_u = (unsigned)__cvta_generic_to_shared(smem_all);

    float acc[2][8][4];
#pragma unroll
    for (int i = 0; i < 2; i++)
#pragma unroll
        for (int j = 0; j < 8; j++)
#pragma unroll
            for (int l = 0; l < 4; l++) acc[i][j][l] = 0.f;

    // zero the halo columns (wl=0, wl=65) of both X buffers once
    if (tid < 128) {
        int bf = tid >> 6, row = (tid >> 4) & 3, side = (tid >> 3) & 1, c = tid & 7;
        smem_all[(bf ? XO1 : XO0) + row * 528 + side * 520 + c] = 0.f;
    }

    auto stage = [&](int chunk, int bf) {
        unsigned sxa = smem_u + 4u * (bf ? XO1 : XO0);
        unsigned swa = smem_u + 4u * (bf ? WO1 : WO0);
        const float* xsrc = g_xr + (size_t)(b * 16 + chunk) * 32768;
        for (int idx = tid; idx < 512; idx += 256) {
            int row = idx >> 7, f4 = idx & 127;
            int ih = 2 * hb - 1 + row;
            bool v = ((unsigned)ih < 64u);
            cp16(sxa + 4u * (row * 528 + 8 + f4 * 4),
                 xsrc + (size_t)(v ? ih : 0) * 512 + f4 * 4, v ? 16 : 0);
        }
        const float* wsrc = g_wr + (size_t)(e * 16 + chunk) * 9216;
        for (int idx = tid; idx < 2304; idx += 256)
            cp16(swa + idx * 16u, wsrc + idx * 4, 16);
    };

    stage(0, 0); cp_commit();
    stage(1, 1); cp_commit();

    for (int k = 0; k < 16; k++) {
        cp_wait1();
        __syncthreads();
        int bf = k & 1;
        const float* sX = smem_all + (bf ? XO1 : XO0);
        const float* sW = smem_all + (bf ? WO1 : WO0);
#pragma unroll
        for (int tap = 0; tap < 9; tap++) {
            int dy = tap / 3, dx = tap - dy * 3;
            const float* wp = sW + tap * 1024 + (ocw * 32 + q) * 8 + 2 * r;
            float2 A0 = *(const float2*)(wp);
            float2 A1 = *(const float2*)(wp + 64);
            float2 A2 = *(const float2*)(wp + 128);
            float2 A3 = *(const float2*)(wp + 192);
            const float* xp = sX + (ph + dy) * 528 + (q + dx) * 8 + 2 * r;
#pragma unroll
            for (int nt = 0; nt < 8; nt++) {
                float2 Bv = *(const float2*)(xp + nt * 64);
                mma8(acc[0][nt], A0.x, A1.x, A0.y, A1.y, Bv.x, Bv.y);
                mma8(acc[1][nt], A2.x, A3.x, A2.y, A3.y, Bv.x, Bv.y);
            }
        }
        __syncthreads();
        if (k + 2 < 16) stage(k + 2, bf);
        cp_commit();
    }

    // ---- stats per 16-oc group ----
    float* red = smem_all + REDE;
#pragma unroll
    for (int mt = 0; mt < 2; mt++) {
        float s1 = 0.f, s2 = 0.f;
#pragma unroll
        for (int nt = 0; nt < 8; nt++)
#pragma unroll
            for (int j = 0; j < 4; j++) {
                float v = acc[mt][nt][j];
                s1 += v; s2 += v * v;
            }
#pragma unroll
        for (int off = 16; off > 0; off >>= 1) {
            s1 += __shfl_xor_sync(0xffffffffu, s1, off);
            s2 += __shfl_xor_sync(0xffffffffu, s2, off);
        }
        if (lane == 0) {
            int g = ocw * 2 + mt;
            red[g * 4 + ph * 2 + 0] = s1;
            red[g * 4 + ph * 2 + 1] = s2;
        }
    }

    // ---- stage outputs [128 oc][132 pitch] ----
    float* stg = smem_all;
#pragma unroll
    for (int mt = 0; mt < 2; mt++)
#pragma unroll
        for (int nt = 0; nt < 8; nt++)
#pragma unroll
            for (int j = 0; j < 4; j++) {
                int ocl = ocw * 32 + mt * 16 + q + 8 * (j >> 1);
                int w = nt * 8 + 2 * r + (j & 1);
                stg[ocl * 132 + ph * 64 + w] = acc[mt][nt][j];
            }
    __syncthreads();
    if (tid < 8) {
        float a = red[tid * 4 + 0] + red[tid * 4 + 2];
        float bq = red[tid * 4 + 1] + red[tid * 4 + 3];
        int slot = (e * NB + b) * 8 + tid;
        g_part_exp[(slot * 32 + hb) * 2 + 0] = a;
        g_part_exp[(slot * 32 + hb) * 2 + 1] = bq;
    }
    size_t base = (size_t)((e * NB + b) * NC) * HWSZ;
    for (int idx = tid; idx < 4096; idx += 256) {
        int ocl = idx >> 5, p4 = (idx & 31) * 4;
        float4 v = *(const float4*)(stg + ocl * 132 + p4);
        int h = 2 * hb + (p4 >> 6), w = p4 & 63;
        *(float4*)(g_z + base + (size_t)ocl * HWSZ + h * 64 + w) = v;
    }
}

// ---------------- finalize stats ----------------
__global__ void k_finalize(int which) {
    const float* part; float* ms; int nper, nslots; float invN;
    if (which == 0)      { part = g_part_exp; ms = g_ms_exp; nper = 32;  nslots = 1024; invN = 1.0f / 65536.0f; }
    else if (which == 1) { part = g_part1;    ms = g_ms1;    nper = 32;  nslots = 128;  invN = 1.0f / 262144.0f; }
    else if (which == 2) { part = g_part2;    ms = g_ms2;    nper = 512; nslots = 128;  invN = 1.0f / 262144.0f; }
    else                 { part = g_part3;    ms = g_ms3;    nper = 16;  nslots = 128;  invN = 1.0f / 16384.0f; }
    int s = blockIdx.x * blockDim.x + threadIdx.x;
    if (s >= nslots) return;
    float s1 = 0.f, s2 = 0.f;
    for (int i = 0; i < nper; i++) {
        s1 += part[(s * nper + i) * 2 + 0];
        s2 += part[(s * nper + i) * 2 + 1];
    }
    float m = s1 * invN;
    float v = s2 * invN - m * m;
    ms[s * 2 + 0] = m;
    ms[s * 2 + 1] = rsqrtf(v + 1e-5f);
}

// ---------------- combine: GN+SiLU+residual+weights -> tf32 permuted --------
__global__ __launch_bounds__(256) void k_combine(const float* __restrict__ x,
                                                 const float* __restrict__ gs,
                                                 const float* __restrict__ gb) {
    int idx = blockIdx.x * 256 + threadIdx.x;   // 1048576 = B*16*4096
    int px = idx & 4095, chunk = (idx >> 12) & 15, b = idx >> 16;
    int h = px >> 6, w = px & 63;
    int patch = ((h >> 4) << 2) + (w >> 4);
    int g = chunk >> 1;
    float res[8];
#pragma unroll
    for (int j = 0; j < 8; j++) {
        int c = chunk * 8 + (j >> 1) + (j & 1) * 4;
        res[j] = x[((b * 128 + c) << 12) + px];
    }
#pragma unroll
    for (int e = 0; e < 8; e++) {
        float m  = g_ms_exp[(((e * NB + b) * 8) + g) * 2 + 0];
        float rs = g_ms_exp[(((e * NB + b) * 8) + g) * 2 + 1];
        float wt = g_wts[patch * 8 + e];
#pragma unroll
        for (int j = 0; j < 8; j++) {
            int c = chunk * 8 + (j >> 1) + (j & 1) * 4;
            float zv = g_z[((size_t)((e * NB + b) * NC + c)) * HWSZ + px];
            float t = (zv - m) * rs * gs[e * NC + c] + gb[e * NC + c];
            res[j] += wt * silu_f(t);
        }
    }
    float4* dst = (float4*)(g_combp + (size_t)idx * 8);
    dst[0] = make_float4(tf32r(res[0]), tf32r(res[1]), tf32r(res[2]), tf32r(res[3]));
    dst[1] = make_float4(tf32r(res[4]), tf32r(res[5]), tf32r(res[6]), tf32r(res[7]));
}

// ---------------- pw1: tf32 mma, block 128hc x 128px, K=128 -----------------
#define P1X0 0
#define P1W0 1024
#define P1X1 2048
#define P1W1 3072
#define RED1 16896
#define PW1F 16928

__global__ __launch_bounds__(256, 2) void k_pw1_mma() {
    int tid = threadIdx.x;
    int wid = tid >> 5, lane = tid & 31;
    int q = lane >> 2, r = lane & 3;
    int ocw = wid >> 1, ph = wid & 1;
    int ht = blockIdx.x, pt = blockIdx.y, b = blockIdx.z;
    unsigned smem_u = (unsigned)__cvta_generic_to_shared(smem_all);

    float acc[2][8][4];
#pragma unroll
    for (int i = 0; i < 2; i++)
#pragma unroll
        for (int j = 0; j < 8; j++)
#pragma unroll
            for (int l = 0; l < 4; l++) acc[i][j][l] = 0.f;

    auto stage = [&](int chunk, int bf) {
        unsigned sxa = smem_u + 4u * (bf ? P1X1 : P1X0);
        unsigned swa = smem_u + 4u * (bf ? P1W1 : P1W0);
        const float* xsrc = g_combp + ((size_t)(b * 16 + chunk) * 4096 + pt * 128) * 8;
        const float* wsrc = g_w1r + (ht * 16 + chunk) * 1024;
        // X tile: 128px*8cp = 1024 floats = 256 cp16; W same
        cp16(sxa + tid * 16u, xsrc + tid * 4, 16);
        cp16(swa + tid * 16u, wsrc + tid * 4, 16);
    };

    stage(0, 0); cp_commit();
    stage(1, 1); cp_commit();

    for (int k = 0; k < 16; k++) {
        cp_wait1();
        __syncthreads();
        int bf = k & 1;
        const float* sX = smem_all + (bf ? P1X1 : P1X0);
        const float* sW = smem_all + (bf ? P1W1 : P1W0);
        const float* wp = sW + (ocw * 32 + q) * 8 + 2 * r;
        float2 A0 = *(const float2*)(wp);
        float2 A1 = *(const float2*)(wp + 64);
        float2 A2 = *(const float2*)(wp + 128);
        float2 A3 = *(const float2*)(wp + 192);
#pragma unroll
        for (int nt = 0; nt < 8; nt++) {
            const float* xp = sX + (ph * 64 + nt * 8 + q) * 8 + 2 * r;
            float2 Bv = *(const float2*)(xp);
            mma8(acc[0][nt], A0.x, A1.x, A0.y, A1.y, Bv.x, Bv.y);
            mma8(acc[1][nt], A2.x, A3.x, A2.y, A3.y, Bv.x, Bv.y);
        }
        __syncthreads();
        if (k + 2 < 16) stage(k + 2, bf);
        cp_commit();
    }

    // stats: whole warp belongs to group ht*2 + (ocw>>1)
    float s1 = 0.f, s2 = 0.f;
#pragma unroll
    for (int i = 0; i < 2; i++)
#pragma unroll
        for (int j = 0; j < 8; j++)
#pragma unroll
            for (int l = 0; l < 4; l++) {
                float v = acc[i][j][l];
                s1 += v; s2 += v * v;
            }
#pragma unroll
    for (int off = 16; off > 0; off >>= 1) {
        s1 += __shfl_xor_sync(0xffffffffu, s1, off);
        s2 += __shfl_xor_sync(0xffffffffu, s2, off);
    }
    float* red = smem_all + RED1;
    if (lane == 0) { red[wid * 2] = s1; red[wid * 2 + 1] = s2; }

    float* stg = smem_all;
#pragma unroll
    for (int mt = 0; mt < 2; mt++)
#pragma unroll
        for (int nt = 0; nt < 8; nt++)
#pragma unroll
            for (int j = 0; j < 4; j++) {
                int hcl = ocw * 32 + mt * 16 + q + 8 * (j >> 1);
                int w = nt * 8 + 2 * r + (j & 1);
                stg[hcl * 132 + ph * 64 + w] = acc[mt][nt][j];
            }
    __syncthreads();
    if (tid < 2) {
        float a = red[tid * 8 + 0] + red[tid * 8 + 2] + red[tid * 8 + 4] + red[tid * 8 + 6];
        float bq = red[tid * 8 + 1] + red[tid * 8 + 3] + red[tid * 8 + 5] + red[tid * 8 + 7];
        int slot = b * 8 + ht * 2 + tid;
        g_part1[(slot * 32 + pt) * 2 + 0] = a;
        g_part1[(slot * 32 + pt) * 2 + 1] = bq;
    }
    for (int idx = tid; idx < 4096; idx += 256) {
        int hcl = idx >> 5, p4 = (idx & 31) * 4;
        float4 v = *(const float4*)(stg + hcl * 132 + p4);
        *(float4*)(g_h1 + (size_t)(b * NHC + ht * 128 + hcl) * HWSZ + pt * 128 + p4) = v;
    }
}

// ---------------- dw ----------------
__global__ __launch_bounds__(256) void k_dw(const float* __restrict__ w_dw,
                                            const float* __restrict__ s1v,
                                            const float* __restrict__ b1v) {
    __shared__ float sa[660];
    __shared__ float red[512];
    int tid = threadIdx.x;
    int ht = blockIdx.x, ch = blockIdx.y, b = blockIdx.z;
    int h0 = ht * 8;
    float m  = g_ms1[(b * 8 + (ch >> 6)) * 2 + 0];
    float rs = g_ms1[(b * 8 + (ch >> 6)) * 2 + 1];
    float sc = s1v[ch], bi = b1v[ch];
    for (int idx = tid; idx < 660; idx += 256) {
        int r = idx / 66, i = idx % 66;
        int hh = h0 - 1 + r, ww = i - 1;
        float v = 0.f;
        if (hh >= 0 && hh < 64 && ww >= 0 && ww < 64) {
            float t = (g_h1[((size_t)(b * NHC + ch) * 64 + hh) * 64 + ww] - m) * rs * sc + bi;
            v = silu_f(t);
        }
        sa[idx] = v;
    }
    __syncthreads();
    float wd[9];
#pragma unroll
    for (int j = 0; j < 9; j++) wd[j] = w_dw[ch * 9 + j];
    float s1 = 0.f, s2 = 0.f;
#pragma unroll
    for (int oo = 0; oo < 2; oo++) {
        int o = tid + oo * 256;
        int r = o >> 6, w = o & 63;
        float a = 0.f;
#pragma unroll
        for (int dr = 0; dr < 3; dr++)
#pragma unroll
            for (int dt = 0; dt < 3; dt++)
                a += sa[(r + dr) * 66 + w + dt] * wd[dr * 3 + dt];
        g_h2[((size_t)(b * NHC + ch) * 64 + h0 + r) * 64 + w] = a;
        s1 += a; s2 += a * a;
    }
    red[tid] = s1; red[256 + tid] = s2;
    __syncthreads();
    for (int st = 128; st > 0; st >>= 1) {
        if (tid < st) { red[tid] += red[tid + st]; red[256 + tid] += red[256 + tid + st]; }
        __syncthreads();
    }
    if (tid == 0) {
        int slot = b * 8 + (ch >> 6);
        int entry = (ch & 63) * 8 + ht;
        g_part2[(slot * 512 + entry) * 2 + 0] = red[0];
        g_part2[(slot * 512 + entry) * 2 + 1] = red[256];
    }
}

// ---------------- pw2 ----------------
__global__ __launch_bounds__(256) void k_pw2(const float* __restrict__ w_pw2,
                                             const float* __restrict__ s2v,
                                             const float* __restrict__ b2v) {
    __shared__ float sA[2048], sW[4096], red[512];
    int tid = threadIdx.x;
    int pt = blockIdx.x, b = blockIdx.y;
    int pg = tid & 15, og = tid >> 4;
    float acc[32];
#pragma unroll
    for (int i = 0; i < 32; i++) acc[i] = 0.f;

    for (int c0 = 0; c0 < 512; c0 += 32) {
        __syncthreads();
        for (int idx = tid; idx < 2048; idx += 256) {
            int kc = idx >> 6, p = idx & 63;
            int hc = c0 + kc;
            int pi = pt * 64 + p;
            int ii = pi >> 5, jj = pi & 31;
            float v = g_h2[((size_t)(b * NHC + hc) * 64 + 2 * ii) * 64 + 2 * jj];
            float m  = g_ms2[(b * 8 + (hc >> 6)) * 2 + 0];
            float rr = g_ms2[(b * 8 + (hc >> 6)) * 2 + 1];
            float t = (v - m) * rr * s2v[hc] + b2v[hc];
            sA[idx] = silu_f(t);
        }
        for (int idx = tid; idx < 4096; idx += 256) {
            int kc = idx >> 7, co = idx & 127;
            sW[idx] = w_pw2[co * NHC + c0 + kc];
        }
        __syncthreads();
        for (int kc = 0; kc < 32; kc++) {
            float a0 = sA[kc * 64 + 4 * pg + 0];
            float a1 = sA[kc * 64 + 4 * pg + 1];
            float a2 = sA[kc * 64 + 4 * pg + 2];
            float a3 = sA[kc * 64 + 4 * pg + 3];
#pragma unroll
            for (int l = 0; l < 8; l++) {
                float wv = sW[kc * 128 + 8 * og + l];
                acc[0 * 8 + l] += a0 * wv;
                acc[1 * 8 + l] += a1 * wv;
                acc[2 * 8 + l] += a2 * wv;
                acc[3 * 8 + l] += a3 * wv;
            }
        }
    }
    float s1 = 0.f, s2 = 0.f;
#pragma unroll
    for (int i = 0; i < 32; i++) { s1 += acc[i]; s2 += acc[i] * acc[i]; }
    red[tid] = s1; red[256 + tid] = s2;
    __syncthreads();
    if ((tid & 31) == 0) {
        float a = 0.f, bq = 0.f;
        for (int i = 0; i < 32; i++) { a += red[tid + i]; bq += red[256 + tid + i]; }
        int g = tid >> 5;
        g_part3[((b * 8 + g) * 16 + pt) * 2 + 0] = a;
        g_part3[((b * 8 + g) * 16 + pt) * 2 + 1] = bq;
    }
#pragma unroll
    for (int k = 0; k < 4; k++) {
        int pi = pt * 64 + 4 * pg + k;
        int ii = pi >> 5, jj = pi & 31;
#pragma unroll
        for (int l = 0; l < 8; l++) {
            int co = 8 * og + l;
            g_h3[((b * NC + co) << 10) + (ii << 5) + jj] = acc[k * 8 + l];
        }
    }
}

// ---------------- final ----------------
__global__ void k_out(float* __restrict__ out,
                      const float* __restrict__ s3v, const float* __restrict__ b3v) {
    int idx = blockIdx.x * 256 + threadIdx.x;
    int co = (idx >> 10) & 127, b = idx >> 17;
    int g = co >> 4;
    float m  = g_ms3[(b * 8 + g) * 2 + 0];
    float rs = g_ms3[(b * 8 + g) * 2 + 1];
    float t = (g_h3[idx] - m) * rs * s3v[co] + b3v[co];
    out[idx] = silu_f(t);
}

// ---------------- launch ----------------
extern "C" void kernel_launch(void* const* d_in, const int* in_sizes, int n_in,
                              void* d_out, int out_size) {
    const float* x      = (const float*)d_in[0];
    const float* w_exp  = (const float*)d_in[1];
    const float* gs_e   = (const float*)d_in[2];
    const float* gb_e   = (const float*)d_in[3];
    const float* w1     = (const float*)d_in[4];
    const float* b1     = (const float*)d_in[5];
    const float* w2     = (const float*)d_in[6];
    const float* b2     = (const float*)d_in[7];
    const float* w_pw1  = (const float*)d_in[8];
    const float* gn1_s  = (const float*)d_in[9];
    const float* gn1_b  = (const float*)d_in[10];
    const float* w_dw   = (const float*)d_in[11];
    const float* gn2_s  = (const float*)d_in[12];
    const float* gn2_b  = (const float*)d_in[13];
    const float* w_pw2  = (const float*)d_in[14];
    const float* gn3_s  = (const float*)d_in[15];
    const float* gn3_b  = (const float*)d_in[16];
    float* out = (float*)d_out;

    static bool attr_done = false;
    if (!attr_done) {
        cudaFuncSetAttribute(k_expert_mma, cudaFuncAttributeMaxDynamicSharedMemorySize,
                             EXPF * 4);
        cudaFuncSetAttribute(k_pw1_mma, cudaFuncAttributeMaxDynamicSharedMemorySize,
                             PW1F * 4);
        attr_done = true;
    }

    k_xform_x<<<4096, 256>>>(x);
    k_xform_w<<<4608, 256>>>(w_exp);
    k_xform_w1<<<256, 256>>>(w_pw1);
    k_router<<<1, 1024>>>(w1, b1, w2, b2);
    k_expert_mma<<<dim3(32, 128), 256, EXPF * 4>>>();
    k_finalize<<<4, 256>>>(0);
    k_combine<<<4096, 256>>>(x, gs_e, gb_e);
    k_pw1_mma<<<dim3(4, 32, 16), 256, PW1F * 4>>>();
    k_finalize<<<4, 256>>>(1);
    k_dw<<<dim3(8, 512, 16), 256>>>(w_dw, gn1_s, gn1_b);
    k_finalize<<<4, 256>>>(2);
    k_pw2<<<dim3(16, 16), 256>>>(w_pw2, gn2_s, gn2_b);
    k_finalize<<<4, 256>>>(3);
    k_out<<<8192, 256>>>(out, gn3_s, gn3_b);
}

// round 6
// speedup vs baseline: 4.5385x; 1.0886x over previous
#include <cuda_runtime.h>
#include <math.h>

// ---------------- problem constants ----------------
#define NB   16
#define NC   128
#define NHC  512
#define HWSZ 4096

// ---------------- scratch ----------------
__device__ float g_z[67108864];      // [E*B][C][HW] expert conv raw
__device__ float g_combp[8388608];   // [B][chunk16][px4096][cp8] tf32
__device__ float g_h1[33554432];
__device__ float g_h2[8388608];      // COMPACT [B][HC][32][32] dw output (even px)
__device__ float g_h3[2097152];
__device__ float g_wts[128];
__device__ float g_xr[8388608];      // [B][chunk16][h][w][cp8] tf32
__device__ float g_wr[1179648];      // [E][chunk16][tap9][oc128][cp8] tf32
__device__ float g_w1r[65536];       // [ht4][chunk16][hcl128][cp8] tf32
__device__ float g_part_exp[1024 * 64 * 2];
__device__ float g_ms_exp[1024 * 2];
__device__ float g_part1[128 * 32 * 2];
__device__ float g_ms1[128 * 2];
__device__ float g_part2[128 * 64 * 2];
__device__ float g_ms2[128 * 2];
__device__ float g_part3[128 * 16 * 2];
__device__ float g_ms3[128 * 2];

__device__ __forceinline__ float silu_f(float x) {
    return x / (1.0f + expf(-x));
}
__device__ __forceinline__ float tf32r(float x) {
    unsigned u;
    asm("cvt.rna.tf32.f32 %0, %1;" : "=r"(u) : "f"(x));
    return __uint_as_float(u);
}
__device__ __forceinline__ void cp16(unsigned s, const void* g, int sz) {
    asm volatile("cp.async.cg.shared.global [%0], [%1], 16, %2;\n"
                 :: "r"(s), "l"(g), "r"(sz) : "memory");
}
__device__ __forceinline__ void cp_commit() {
    asm volatile("cp.async.commit_group;\n" ::: "memory");
}
__device__ __forceinline__ void cp_wait1() {
    asm volatile("cp.async.wait_group 1;\n" ::: "memory");
}
__device__ __forceinline__ void mma8(float* c, float a0, float a1, float a2, float a3,
                                     float b0, float b1) {
    asm volatile("mma.sync.aligned.m16n8k8.row.col.f32.tf32.tf32.f32 "
                 "{%0,%1,%2,%3}, {%4,%5,%6,%7}, {%8,%9}, {%0,%1,%2,%3};"
                 : "+f"(c[0]), "+f"(c[1]), "+f"(c[2]), "+f"(c[3])
                 : "r"(__float_as_uint(a0)), "r"(__float_as_uint(a1)),
                   "r"(__float_as_uint(a2)), "r"(__float_as_uint(a3)),
                   "r"(__float_as_uint(b0)), "r"(__float_as_uint(b1)));
}

// ---------------- transforms (tf32-round + permute) ----------
// cp = (c&3)*2 + (c>>2);  inverse: c = (cp>>1) + (cp&1)*4
__global__ void k_xform_x(const float* __restrict__ x) {
    int idx = blockIdx.x * 256 + threadIdx.x;   // 1048576
    int w = idx & 63, h = (idx >> 6) & 63, chunk = (idx >> 12) & 15, b = idx >> 16;
    float o[8];
#pragma unroll
    for (int j = 0; j < 8; j++) {
        int c = chunk * 8 + (j >> 1) + (j & 1) * 4;
        o[j] = tf32r(x[((b * 128 + c) << 12) + (h << 6) + w]);
    }
    float4* dst = (float4*)(g_xr + (size_t)idx * 8);
    dst[0] = make_float4(o[0], o[1], o[2], o[3]);
    dst[1] = make_float4(o[4], o[5], o[6], o[7]);
}

__global__ void k_xform_w(const float* __restrict__ w_exp) {
    int idx = blockIdx.x * 256 + threadIdx.x;   // 1179648
    int cp = idx & 7, ocl = (idx >> 3) & 127;
    int t2 = idx >> 10;
    int tap = t2 % 9, ec = t2 / 9;
    int chunk = ec & 15, e = ec >> 4;
    int c = chunk * 8 + (cp >> 1) + (cp & 1) * 4;
    g_wr[idx] = tf32r(w_exp[((e * 128 + ocl) * 128 + c) * 9 + tap]);
}

__global__ void k_xform_w1(const float* __restrict__ w_pw1) {
    int idx = blockIdx.x * 256 + threadIdx.x;   // 65536
    int cp = idx & 7, hcl = (idx >> 3) & 127, chunk = (idx >> 10) & 15, ht = idx >> 14;
    int c = chunk * 8 + (cp >> 1) + (cp & 1) * 4;
    g_w1r[idx] = tf32r(w_pw1[(ht * 128 + hcl) * 128 + c]);
}

// ---------------- router ----------------
__global__ void k_router(const float* __restrict__ w1, const float* __restrict__ b1,
                         const float* __restrict__ w2, const float* __restrict__ b2) {
    __shared__ float feats[16 * 32];
    __shared__ float hid[16 * 64];
    __shared__ float lg[16 * 8];
    int tid = threadIdx.x;
    if (tid < 512) {
        int p = tid >> 5, f = tid & 31;
        int py = p >> 2, px = p & 3;
        int k = f & 7, kind = f >> 3;
        float freq = exp2f((float)k) * 3.14159265358979323846f;
        float cy = (py + 0.5f) * 0.25f;
        float cx = (px + 0.5f) * 0.25f;
        float v;
        if (kind == 0)      v = sinf(cy * freq);
        else if (kind == 1) v = cosf(cy * freq);
        else if (kind == 2) v = sinf(cx * freq);
        else                v = cosf(cx * freq);
        feats[p * 32 + f] = v;
    }
    __syncthreads();
    {
        int p = tid >> 6, hh = tid & 63;
        float a = b1[hh];
        for (int f = 0; f < 32; f++) a += feats[p * 32 + f] * w1[f * 64 + hh];
        hid[p * 64 + hh] = silu_f(a);
    }
    __syncthreads();
    if (tid < 128) {
        int p = tid >> 3, e = tid & 7;
        float a = b2[e];
        for (int hh = 0; hh < 64; hh++) a += hid[p * 64 + hh] * w2[hh * 8 + e];
        lg[p * 8 + e] = a;
    }
    __syncthreads();
    if (tid < 16) {
        float mx = -1e30f;
        for (int e = 0; e < 8; e++) mx = fmaxf(mx, lg[tid * 8 + e]);
        float ex[8], s = 0.f;
        for (int e = 0; e < 8; e++) { ex[e] = expf(lg[tid * 8 + e] - mx); s += ex[e]; }
        float inv = 1.0f / s;
        for (int e = 0; e < 8; e++) g_wts[tid * 8 + e] = ex[e] * inv;
    }
}

// ---------------- expert conv: tf32 mma, block 128oc x 256px ----------------
// 8 warps = ocw(2: 64oc) x orow(4: rows). grid (hb=16, e*16+b=128).
#define XA0 0
#define XA1 3168
#define WA0 6336
#define WA1 15552
#define EXPF 24768

extern __shared__ float smem_all[];

__global__ __launch_bounds__(256, 1) void k_expert_mma() {
    int tid = threadIdx.x;
    int wid = tid >> 5, lane = tid & 31;
    int q = lane >> 2, r = lane & 3;
    int ocw = wid & 1, orow = wid >> 1;
    int hb = blockIdx.x;
    int b = blockIdx.y & 15, e = blockIdx.y >> 4;
    unsigned smem_u = (unsigned)__cvta_generic_to_shared(smem_all);

    float acc[4][8][4];
#pragma unroll
    for (int i = 0; i < 4; i++)
#pragma unroll
        for (int j = 0; j < 8; j++)
#pragma unroll
            for (int l = 0; l < 4; l++) acc[i][j][l] = 0.f;

    // zero halo columns (wl=0, wl=65) of both X buffers
    if (tid < 192) {
        int bf = tid / 96, t = tid % 96;
        int row = t >> 4, side = (t >> 3) & 1, c = t & 7;
        smem_all[(bf ? XA1 : XA0) + row * 528 + (side ? 65 : 0) * 8 + c] = 0.f;
    }

    auto stage = [&](int chunk, int bf) {
        unsigned sx = smem_u + 4u * (bf ? XA1 : XA0);
        unsigned sw = smem_u + 4u * (bf ? WA1 : WA0);
        const float* xs = g_xr + (size_t)(b * 16 + chunk) * 32768;
        for (int idx = tid; idx < 768; idx += 256) {
            int row = idx >> 7, f4 = idx & 127;
            int ih = 4 * hb - 1 + row;
            bool v = ((unsigned)ih < 64u);
            cp16(sx + 4u * (row * 528 + 8 + f4 * 4),
                 xs + (size_t)(v ? ih : 0) * 512 + f4 * 4, v ? 16 : 0);
        }
        const float* ws = g_wr + (size_t)(e * 16 + chunk) * 9216;
        for (int idx = tid; idx < 2304; idx += 256)
            cp16(sw + idx * 16u, ws + idx * 4, 16);
    };

    stage(0, 0); cp_commit();
    stage(1, 1); cp_commit();

    for (int c = 0; c < 16; c++) {
        cp_wait1();
        __syncthreads();
        int bf = c & 1;
        const float* sX = smem_all + (bf ? XA1 : XA0);
        const float* sW = smem_all + (bf ? WA1 : WA0);
#pragma unroll
        for (int tap = 0; tap < 9; tap++) {
            int dy = tap / 3, dx = tap - dy * 3;
            const float* wp = sW + tap * 1024 + (ocw * 64 + q) * 8 + 2 * r;
            float2 A[4][2];
#pragma unroll
            for (int mt = 0; mt < 4; mt++) {
                A[mt][0] = *(const float2*)(wp + mt * 128);
                A[mt][1] = *(const float2*)(wp + mt * 128 + 64);
            }
            const float* xp = sX + (orow + dy) * 528 + (q + dx) * 8 + 2 * r;
#pragma unroll
            for (int nt = 0; nt < 8; nt++) {
                float2 Bv = *(const float2*)(xp + nt * 64);
#pragma unroll
                for (int mt = 0; mt < 4; mt++)
                    mma8(acc[mt][nt], A[mt][0].x, A[mt][1].x, A[mt][0].y, A[mt][1].y,
                         Bv.x, Bv.y);
            }
        }
        __syncthreads();
        if (c + 2 < 16) stage(c + 2, bf);
        cp_commit();
    }

    // ---- stats: one 16-oc group per m-tile, reduce across whole warp ----
#pragma unroll
    for (int mt = 0; mt < 4; mt++) {
        float s1 = 0.f, s2 = 0.f;
#pragma unroll
        for (int nt = 0; nt < 8; nt++)
#pragma unroll
            for (int j = 0; j < 4; j++) {
                float v = acc[mt][nt][j];
                s1 += v; s2 += v * v;
            }
#pragma unroll
        for (int off = 16; off > 0; off >>= 1) {
            s1 += __shfl_xor_sync(0xffffffffu, s1, off);
            s2 += __shfl_xor_sync(0xffffffffu, s2, off);
        }
        if (lane == 0) {
            int g = ocw * 4 + mt;
            int slot = (e * NB + b) * 8 + g;
            g_part_exp[(slot * 64 + hb * 4 + orow) * 2 + 0] = s1;
            g_part_exp[(slot * 64 + hb * 4 + orow) * 2 + 1] = s2;
        }
    }

    // ---- output: two staging passes of 128 oc x 128 px ----
    float* stg = smem_all;
    size_t zbase = (size_t)((e * NB + b) * NC) * HWSZ;
#pragma unroll
    for (int p = 0; p < 2; p++) {
        __syncthreads();
        if ((orow >> 1) == p) {
#pragma unroll
            for (int mt = 0; mt < 4; mt++)
#pragma unroll
                for (int nt = 0; nt < 8; nt++)
#pragma unroll
                    for (int j = 0; j < 4; j++) {
                        int oc = ocw * 64 + mt * 16 + q + 8 * (j >> 1);
                        int px = (orow & 1) * 64 + nt * 8 + 2 * r + (j & 1);
                        stg[oc * 132 + px] = acc[mt][nt][j];
                    }
        }
        __syncthreads();
        for (int idx = tid; idx < 4096; idx += 256) {
            int oc = idx >> 5, p4 = (idx & 31) * 4;
            float4 v = *(const float4*)(stg + oc * 132 + p4);
            int h = 4 * hb + 2 * p + (p4 >> 6), w = p4 & 63;
            *(float4*)(g_z + zbase + (size_t)oc * HWSZ + h * 64 + w) = v;
        }
    }
}

// ---------------- finalize stats ----------------
__global__ void k_finalize(int which) {
    const float* part; float* ms; int nper, nslots; float invN;
    if (which == 0)      { part = g_part_exp; ms = g_ms_exp; nper = 64; nslots = 1024; invN = 1.0f / 65536.0f; }
    else if (which == 1) { part = g_part1;    ms = g_ms1;    nper = 32; nslots = 128;  invN = 1.0f / 262144.0f; }
    else if (which == 2) { part = g_part2;    ms = g_ms2;    nper = 64; nslots = 128;  invN = 1.0f / 262144.0f; }
    else                 { part = g_part3;    ms = g_ms3;    nper = 16; nslots = 128;  invN = 1.0f / 16384.0f; }
    int s = blockIdx.x * blockDim.x + threadIdx.x;
    if (s >= nslots) return;
    float s1 = 0.f, s2 = 0.f;
    for (int i = 0; i < nper; i++) {
        s1 += part[(s * nper + i) * 2 + 0];
        s2 += part[(s * nper + i) * 2 + 1];
    }
    float m = s1 * invN;
    float v = s2 * invN - m * m;
    ms[s * 2 + 0] = m;
    ms[s * 2 + 1] = rsqrtf(v + 1e-5f);
}

// ---------------- combine ----------------
__global__ __launch_bounds__(256) void k_combine(const float* __restrict__ x,
                                                 const float* __restrict__ gs,
                                                 const float* __restrict__ gb) {
    int idx = blockIdx.x * 256 + threadIdx.x;   // 1048576 = B*16*4096
    int px = idx & 4095, chunk = (idx >> 12) & 15, b = idx >> 16;
    int h = px >> 6, w = px & 63;
    int patch = ((h >> 4) << 2) + (w >> 4);
    int g = chunk >> 1;
    float res[8];
#pragma unroll
    for (int j = 0; j < 8; j++) {
        int c = chunk * 8 + (j >> 1) + (j & 1) * 4;
        res[j] = x[((b * 128 + c) << 12) + px];
    }
#pragma unroll
    for (int e = 0; e < 8; e++) {
        float m  = g_ms_exp[(((e * NB + b) * 8) + g) * 2 + 0];
        float rs = g_ms_exp[(((e * NB + b) * 8) + g) * 2 + 1];
        float wt = g_wts[patch * 8 + e];
#pragma unroll
        for (int j = 0; j < 8; j++) {
            int c = chunk * 8 + (j >> 1) + (j & 1) * 4;
            float zv = g_z[((size_t)((e * NB + b) * NC + c)) * HWSZ + px];
            float t = (zv - m) * rs * gs[e * NC + c] + gb[e * NC + c];
            res[j] += wt * silu_f(t);
        }
    }
    float4* dst = (float4*)(g_combp + (size_t)idx * 8);
    dst[0] = make_float4(tf32r(res[0]), tf32r(res[1]), tf32r(res[2]), tf32r(res[3]));
    dst[1] = make_float4(tf32r(res[4]), tf32r(res[5]), tf32r(res[6]), tf32r(res[7]));
}

// ---------------- pw1: mma.sync tf32, block 128hc x 128px ----------------
#define P1X0 0
#define P1W0 1024
#define P1X1 2048
#define P1W1 3072
#define RED1 16896
#define PW1F 16928

__global__ __launch_bounds__(256, 2) void k_pw1_mma() {
    int tid = threadIdx.x;
    int wid = tid >> 5, lane = tid & 31;
    int q = lane >> 2, r = lane & 3;
    int ocw = wid >> 1, ph = wid & 1;
    int ht = blockIdx.x, pt = blockIdx.y, b = blockIdx.z;
    unsigned smem_u = (unsigned)__cvta_generic_to_shared(smem_all);

    float acc[2][8][4];
#pragma unroll
    for (int i = 0; i < 2; i++)
#pragma unroll
        for (int j = 0; j < 8; j++)
#pragma unroll
            for (int l = 0; l < 4; l++) acc[i][j][l] = 0.f;

    auto stage = [&](int chunk, int bf) {
        unsigned sxa = smem_u + 4u * (bf ? P1X1 : P1X0);
        unsigned swa = smem_u + 4u * (bf ? P1W1 : P1W0);
        const float* xsrc = g_combp + ((size_t)(b * 16 + chunk) * 4096 + pt * 128) * 8;
        const float* wsrc = g_w1r + (ht * 16 + chunk) * 1024;
        cp16(sxa + tid * 16u, xsrc + tid * 4, 16);
        cp16(swa + tid * 16u, wsrc + tid * 4, 16);
    };

    stage(0, 0); cp_commit();
    stage(1, 1); cp_commit();

    for (int k = 0; k < 16; k++) {
        cp_wait1();
        __syncthreads();
        int bf = k & 1;
        const float* sX = smem_all + (bf ? P1X1 : P1X0);
        const float* sW = smem_all + (bf ? P1W1 : P1W0);
        const float* wp = sW + (ocw * 32 + q) * 8 + 2 * r;
        float2 A0 = *(const float2*)(wp);
        float2 A1 = *(const float2*)(wp + 64);
        float2 A2 = *(const float2*)(wp + 128);
        float2 A3 = *(const float2*)(wp + 192);
#pragma unroll
        for (int nt = 0; nt < 8; nt++) {
            const float* xp = sX + (ph * 64 + nt * 8 + q) * 8 + 2 * r;
            float2 Bv = *(const float2*)(xp);
            mma8(acc[0][nt], A0.x, A1.x, A0.y, A1.y, Bv.x, Bv.y);
            mma8(acc[1][nt], A2.x, A3.x, A2.y, A3.y, Bv.x, Bv.y);
        }
        __syncthreads();
        if (k + 2 < 16) stage(k + 2, bf);
        cp_commit();
    }

    float s1 = 0.f, s2 = 0.f;
#pragma unroll
    for (int i = 0; i < 2; i++)
#pragma unroll
        for (int j = 0; j < 8; j++)
#pragma unroll
            for (int l = 0; l < 4; l++) {
                float v = acc[i][j][l];
                s1 += v; s2 += v * v;
            }
#pragma unroll
    for (int off = 16; off > 0; off >>= 1) {
        s1 += __shfl_xor_sync(0xffffffffu, s1, off);
        s2 += __shfl_xor_sync(0xffffffffu, s2, off);
    }
    float* red = smem_all + RED1;
    if (lane == 0) { red[wid * 2] = s1; red[wid * 2 + 1] = s2; }

    float* stg = smem_all;
#pragma unroll
    for (int mt = 0; mt < 2; mt++)
#pragma unroll
        for (int nt = 0; nt < 8; nt++)
#pragma unroll
            for (int j = 0; j < 4; j++) {
                int hcl = ocw * 32 + mt * 16 + q + 8 * (j >> 1);
                int w = nt * 8 + 2 * r + (j & 1);
                stg[hcl * 132 + ph * 64 + w] = acc[mt][nt][j];
            }
    __syncthreads();
    if (tid < 2) {
        float a = red[tid * 8 + 0] + red[tid * 8 + 2] + red[tid * 8 + 4] + red[tid * 8 + 6];
        float bq = red[tid * 8 + 1] + red[tid * 8 + 3] + red[tid * 8 + 5] + red[tid * 8 + 7];
        int slot = b * 8 + ht * 2 + tid;
        g_part1[(slot * 32 + pt) * 2 + 0] = a;
        g_part1[(slot * 32 + pt) * 2 + 1] = bq;
    }
    for (int idx = tid; idx < 4096; idx += 256) {
        int hcl = idx >> 5, p4 = (idx & 31) * 4;
        float4 v = *(const float4*)(stg + hcl * 132 + p4);
        *(float4*)(g_h1 + (size_t)(b * NHC + ht * 128 + hcl) * HWSZ + pt * 128 + p4) = v;
    }
}

// ---------------- dw: one block per (channel, b); compact stride-2 output ---
__global__ __launch_bounds__(256) void k_dw(const float* __restrict__ w_dw,
                                            const float* __restrict__ s1v,
                                            const float* __restrict__ b1v) {
    __shared__ float sa[4356];   // 66 x 66 with halo
    __shared__ float red[512];
    int tid = threadIdx.x;
    int ch = blockIdx.x, b = blockIdx.y;
    float m  = g_ms1[(b * 8 + (ch >> 6)) * 2 + 0];
    float rs = g_ms1[(b * 8 + (ch >> 6)) * 2 + 1];
    float sc = s1v[ch], bi = b1v[ch];
    for (int idx = tid; idx < 4356; idx += 256) sa[idx] = 0.f;
    __syncthreads();
    const float* src = g_h1 + (size_t)(b * NHC + ch) * 4096;
    for (int idx = tid; idx < 1024; idx += 256) {
        int r = idx >> 4, w4 = (idx & 15) * 4;
        float4 v = *(const float4*)(src + r * 64 + w4);
        float* d = sa + (r + 1) * 66 + 1 + w4;
        d[0] = silu_f((v.x - m) * rs * sc + bi);
        d[1] = silu_f((v.y - m) * rs * sc + bi);
        d[2] = silu_f((v.z - m) * rs * sc + bi);
        d[3] = silu_f((v.w - m) * rs * sc + bi);
    }
    __syncthreads();
    float wd[9];
#pragma unroll
    for (int j = 0; j < 9; j++) wd[j] = w_dw[ch * 9 + j];
    int r = tid >> 2, w0 = (tid & 3) * 16;
    float s1 = 0.f, s2 = 0.f;
    float* orow = g_h2 + (size_t)(b * NHC + ch) * 1024 + (r >> 1) * 32;
    bool reven = (r & 1) == 0;
#pragma unroll
    for (int k = 0; k < 16; k++) {
        int w = w0 + k;
        float a = 0.f;
#pragma unroll
        for (int dr = 0; dr < 3; dr++)
#pragma unroll
            for (int dt = 0; dt < 3; dt++)
                a += sa[(r + dr) * 66 + w + dt] * wd[dr * 3 + dt];
        s1 += a; s2 += a * a;
        if (reven && !(w & 1)) orow[w >> 1] = a;
    }
    red[tid] = s1; red[256 + tid] = s2;
    __syncthreads();
    for (int st = 128; st > 0; st >>= 1) {
        if (tid < st) { red[tid] += red[tid + st]; red[256 + tid] += red[256 + tid + st]; }
        __syncthreads();
    }
    if (tid == 0) {
        int slot = b * 8 + (ch >> 6);
        g_part2[(slot * 64 + (ch & 63)) * 2 + 0] = red[0];
        g_part2[(slot * 64 + (ch & 63)) * 2 + 1] = red[256];
    }
}

// ---------------- pw2 (reads compact h2) ----------------
__global__ __launch_bounds__(256) void k_pw2(const float* __restrict__ w_pw2,
                                             const float* __restrict__ s2v,
                                             const float* __restrict__ b2v) {
    __shared__ float sA[2048], sW[4096], red[512];
    int tid = threadIdx.x;
    int pt = blockIdx.x, b = blockIdx.y;
    int pg = tid & 15, og = tid >> 4;
    float acc[32];
#pragma unroll
    for (int i = 0; i < 32; i++) acc[i] = 0.f;

    for (int c0 = 0; c0 < 512; c0 += 32) {
        __syncthreads();
        for (int idx = tid; idx < 2048; idx += 256) {
            int kc = idx >> 6, p = idx & 63;
            int hc = c0 + kc;
            float v = g_h2[(size_t)(b * NHC + hc) * 1024 + pt * 64 + p];
            float m  = g_ms2[(b * 8 + (hc >> 6)) * 2 + 0];
            float rr = g_ms2[(b * 8 + (hc >> 6)) * 2 + 1];
            float t = (v - m) * rr * s2v[hc] + b2v[hc];
            sA[idx] = silu_f(t);
        }
        for (int idx = tid; idx < 4096; idx += 256) {
            int kc = idx >> 7, co = idx & 127;
            sW[idx] = w_pw2[co * NHC + c0 + kc];
        }
        __syncthreads();
        for (int kc = 0; kc < 32; kc++) {
            float a0 = sA[kc * 64 + 4 * pg + 0];
            float a1 = sA[kc * 64 + 4 * pg + 1];
            float a2 = sA[kc * 64 + 4 * pg + 2];
            float a3 = sA[kc * 64 + 4 * pg + 3];
#pragma unroll
            for (int l = 0; l < 8; l++) {
                float wv = sW[kc * 128 + 8 * og + l];
                acc[0 * 8 + l] += a0 * wv;
                acc[1 * 8 + l] += a1 * wv;
                acc[2 * 8 + l] += a2 * wv;
                acc[3 * 8 + l] += a3 * wv;
            }
        }
    }
    float s1 = 0.f, s2 = 0.f;
#pragma unroll
    for (int i = 0; i < 32; i++) { s1 += acc[i]; s2 += acc[i] * acc[i]; }
    red[tid] = s1; red[256 + tid] = s2;
    __syncthreads();
    if ((tid & 31) == 0) {
        float a = 0.f, bq = 0.f;
        for (int i = 0; i < 32; i++) { a += red[tid + i]; bq += red[256 + tid + i]; }
        int g = tid >> 5;
        g_part3[((b * 8 + g) * 16 + pt) * 2 + 0] = a;
        g_part3[((b * 8 + g) * 16 + pt) * 2 + 1] = bq;
    }
#pragma unroll
    for (int k = 0; k < 4; k++) {
        int pi = pt * 64 + 4 * pg + k;
        int ii = pi >> 5, jj = pi & 31;
#pragma unroll
        for (int l = 0; l < 8; l++) {
            int co = 8 * og + l;
            g_h3[((b * NC + co) << 10) + (ii << 5) + jj] = acc[k * 8 + l];
        }
    }
}

// ---------------- final ----------------
__global__ void k_out(float* __restrict__ out,
                      const float* __restrict__ s3v, const float* __restrict__ b3v) {
    int idx = blockIdx.x * 256 + threadIdx.x;
    int co = (idx >> 10) & 127, b = idx >> 17;
    int g = co >> 4;
    float m  = g_ms3[(b * 8 + g) * 2 + 0];
    float rs = g_ms3[(b * 8 + g) * 2 + 1];
    float t = (g_h3[idx] - m) * rs * s3v[co] + b3v[co];
    out[idx] = silu_f(t);
}

// ---------------- launch ----------------
extern "C" void kernel_launch(void* const* d_in, const int* in_sizes, int n_in,
                              void* d_out, int out_size) {
    const float* x      = (const float*)d_in[0];
    const float* w_exp  = (const float*)d_in[1];
    const float* gs_e   = (const float*)d_in[2];
    const float* gb_e   = (const float*)d_in[3];
    const float* w1     = (const float*)d_in[4];
    const float* b1     = (const float*)d_in[5];
    const float* w2     = (const float*)d_in[6];
    const float* b2     = (const float*)d_in[7];
    const float* w_pw1  = (const float*)d_in[8];
    const float* gn1_s  = (const float*)d_in[9];
    const float* gn1_b  = (const float*)d_in[10];
    const float* w_dw   = (const float*)d_in[11];
    const float* gn2_s  = (const float*)d_in[12];
    const float* gn2_b  = (const float*)d_in[13];
    const float* w_pw2  = (const float*)d_in[14];
    const float* gn3_s  = (const float*)d_in[15];
    const float* gn3_b  = (const float*)d_in[16];
    float* out = (float*)d_out;

    static bool attr_done = false;
    if (!attr_done) {
        cudaFuncSetAttribute(k_expert_mma, cudaFuncAttributeMaxDynamicSharedMemorySize,
                             EXPF * 4);
        cudaFuncSetAttribute(k_pw1_mma, cudaFuncAttributeMaxDynamicSharedMemorySize,
                             PW1F * 4);
        attr_done = true;
    }

    k_xform_x<<<4096, 256>>>(x);
    k_xform_w<<<4608, 256>>>(w_exp);
    k_xform_w1<<<256, 256>>>(w_pw1);
    k_router<<<1, 1024>>>(w1, b1, w2, b2);
    k_expert_mma<<<dim3(16, 128), 256, EXPF * 4>>>();
    k_finalize<<<4, 256>>>(0);
    k_combine<<<4096, 256>>>(x, gs_e, gb_e);
    k_pw1_mma<<<dim3(4, 32, 16), 256, PW1F * 4>>>();
    k_finalize<<<4, 256>>>(1);
    k_dw<<<dim3(512, 16), 256>>>(w_dw, gn1_s, gn1_b);
    k_finalize<<<4, 256>>>(2);
    k_pw2<<<dim3(16, 16), 256>>>(w_pw2, gn2_s, gn2_b);
    k_finalize<<<4, 256>>>(3);
    k_out<<<8192, 256>>>(out, gn3_s, gn3_b);
}

// round 7
// speedup vs baseline: 6.2308x; 1.3729x over previous
#include <cuda_runtime.h>
#include <cuda_fp16.h>
#include <math.h>

// ---------------- problem constants ----------------
#define NB   16
#define NC   128
#define NHC  512
#define HWSZ 4096

// ---------------- scratch ----------------
__device__ __half g_z[67108864];     // [E*B][C][HW] expert conv raw (fp16)
__device__ __half g_combp[8388608];  // [B][chunk8][px4096][16kp] fp16
__device__ float  g_h1[33554432];
__device__ float  g_h2[8388608];     // COMPACT [B][HC][32][32]
__device__ float  g_h3[2097152];
__device__ float  g_wts[128];
__device__ __half g_xr[8388608];     // [B][chunk8][h][w][16kp]
__device__ __half g_wr[1179648];     // [E][chunk8][tap9][oc128][16kp]
__device__ __half g_w1r[65536];      // [ht4][chunk8][hcl128][16kp]
__device__ float g_part_exp[1024 * 64 * 2];
__device__ float g_ms_exp[1024 * 2];
__device__ float g_part1[128 * 32 * 2];
__device__ float g_ms1[128 * 2];
__device__ float g_part2[128 * 64 * 2];
__device__ float g_ms2[128 * 2];
__device__ float g_part3[128 * 16 * 2];
__device__ float g_ms3[128 * 2];

__device__ __forceinline__ float silu_f(float x) {
    return x / (1.0f + expf(-x));
}
// permuted k index: j in [0,16) -> k, so thread r's 4 contiguous halves are
// k = {2r, 2r+1, 2r+8, 2r+9}
__device__ __forceinline__ int kmap(int j) {
    return ((j >> 2) * 2) + (j & 1) + ((j >> 1) & 1) * 8;
}
__device__ __forceinline__ void cp16(unsigned s, const void* g, int sz) {
    asm volatile("cp.async.cg.shared.global [%0], [%1], 16, %2;\n"
                 :: "r"(s), "l"(g), "r"(sz) : "memory");
}
__device__ __forceinline__ void cp_commit() {
    asm volatile("cp.async.commit_group;\n" ::: "memory");
}
__device__ __forceinline__ void cp_wait1() {
    asm volatile("cp.async.wait_group 1;\n" ::: "memory");
}
__device__ __forceinline__ void mma16(float* c, unsigned a0, unsigned a1, unsigned a2,
                                      unsigned a3, unsigned b0, unsigned b1) {
    asm volatile("mma.sync.aligned.m16n8k16.row.col.f32.f16.f16.f32 "
                 "{%0,%1,%2,%3}, {%4,%5,%6,%7}, {%8,%9}, {%0,%1,%2,%3};"
                 : "+f"(c[0]), "+f"(c[1]), "+f"(c[2]), "+f"(c[3])
                 : "r"(a0), "r"(a1), "r"(a2), "r"(a3), "r"(b0), "r"(b1));
}

// ---------------- transforms (fp16 + permute) ----------
__global__ void k_xform_x(const float* __restrict__ x) {
    int idx = blockIdx.x * 256 + threadIdx.x;   // 524288
    int w = idx & 63, h = (idx >> 6) & 63, chunk = (idx >> 12) & 7, b = idx >> 15;
    __align__(16) __half o[16];
#pragma unroll
    for (int j = 0; j < 16; j++) {
        int c = chunk * 16 + kmap(j);
        o[j] = __float2half(x[((b * 128 + c) << 12) + (h << 6) + w]);
    }
    uint4* dst = (uint4*)(g_xr + (size_t)idx * 16);
    dst[0] = ((uint4*)o)[0];
    dst[1] = ((uint4*)o)[1];
}

__global__ void k_xform_w(const float* __restrict__ w_exp) {
    int idx = blockIdx.x * 256 + threadIdx.x;   // 73728
    int oc = idx & 127;
    int t2 = idx >> 7;
    int tap = t2 % 9, ec = t2 / 9;
    int chunk = ec & 7, e = ec >> 3;
    __align__(16) __half o[16];
#pragma unroll
    for (int j = 0; j < 16; j++) {
        int c = chunk * 16 + kmap(j);
        o[j] = __float2half(w_exp[((e * 128 + oc) * 128 + c) * 9 + tap]);
    }
    uint4* dst = (uint4*)(g_wr + (size_t)idx * 16);
    dst[0] = ((uint4*)o)[0];
    dst[1] = ((uint4*)o)[1];
}

__global__ void k_xform_w1(const float* __restrict__ w_pw1) {
    int idx = blockIdx.x * 256 + threadIdx.x;   // 4096
    int hcl = idx & 127, chunk = (idx >> 7) & 7, ht = idx >> 10;
    __align__(16) __half o[16];
#pragma unroll
    for (int j = 0; j < 16; j++) {
        int c = chunk * 16 + kmap(j);
        o[j] = __float2half(w_pw1[(ht * 128 + hcl) * 128 + c]);
    }
    uint4* dst = (uint4*)(g_w1r + (size_t)idx * 16);
    dst[0] = ((uint4*)o)[0];
    dst[1] = ((uint4*)o)[1];
}

// ---------------- router ----------------
__global__ void k_router(const float* __restrict__ w1, const float* __restrict__ b1,
                         const float* __restrict__ w2, const float* __restrict__ b2) {
    __shared__ float feats[16 * 32];
    __shared__ float hid[16 * 64];
    __shared__ float lg[16 * 8];
    int tid = threadIdx.x;
    if (tid < 512) {
        int p = tid >> 5, f = tid & 31;
        int py = p >> 2, px = p & 3;
        int k = f & 7, kind = f >> 3;
        float freq = exp2f((float)k) * 3.14159265358979323846f;
        float cy = (py + 0.5f) * 0.25f;
        float cx = (px + 0.5f) * 0.25f;
        float v;
        if (kind == 0)      v = sinf(cy * freq);
        else if (kind == 1) v = cosf(cy * freq);
        else if (kind == 2) v = sinf(cx * freq);
        else                v = cosf(cx * freq);
        feats[p * 32 + f] = v;
    }
    __syncthreads();
    {
        int p = tid >> 6, hh = tid & 63;
        float a = b1[hh];
        for (int f = 0; f < 32; f++) a += feats[p * 32 + f] * w1[f * 64 + hh];
        hid[p * 64 + hh] = silu_f(a);
    }
    __syncthreads();
    if (tid < 128) {
        int p = tid >> 3, e = tid & 7;
        float a = b2[e];
        for (int hh = 0; hh < 64; hh++) a += hid[p * 64 + hh] * w2[hh * 8 + e];
        lg[p * 8 + e] = a;
    }
    __syncthreads();
    if (tid < 16) {
        float mx = -1e30f;
        for (int e = 0; e < 8; e++) mx = fmaxf(mx, lg[tid * 8 + e]);
        float ex[8], s = 0.f;
        for (int e = 0; e < 8; e++) { ex[e] = expf(lg[tid * 8 + e] - mx); s += ex[e]; }
        float inv = 1.0f / s;
        for (int e = 0; e < 8; e++) g_wts[tid * 8 + e] = ex[e] * inv;
    }
}

// ---------------- expert conv: fp16 mma m16n8k16, block 128oc x 256px -------
// 8 warps = ocw(2: 64oc) x orow(4). grid (hb=16, e*16+b=128). K = 8 chunks x 16c.
// X buf: 6 rows x 66 px x 32B = 12672B = 3168 fl; W buf: 9 x 128 x 32B = 9216 fl.
#define XA0 0
#define XA1 3168
#define WA0 6336
#define WA1 15552
#define EXPF 24768

extern __shared__ float smem_all[];

__global__ __launch_bounds__(256, 1) void k_expert_mma() {
    int tid = threadIdx.x;
    int wid = tid >> 5, lane = tid & 31;
    int q = lane >> 2, r = lane & 3;
    int ocw = wid & 1, orow = wid >> 1;
    int hb = blockIdx.x;
    int b = blockIdx.y & 15, e = blockIdx.y >> 4;
    unsigned smem_u = (unsigned)__cvta_generic_to_shared(smem_all);

    float acc[4][8][4];
#pragma unroll
    for (int i = 0; i < 4; i++)
#pragma unroll
        for (int j = 0; j < 8; j++)
#pragma unroll
            for (int l = 0; l < 4; l++) acc[i][j][l] = 0.f;

    // zero halo pixels (px 0 and 65) of both X buffers: 32B each, as 8 floats
    if (tid < 192) {
        int bf = tid / 96, t = tid % 96;
        int row = t >> 4, side = (t >> 3) & 1, f = t & 7;
        smem_all[(bf ? XA1 : XA0) + row * 528 + (side ? 65 : 0) * 8 + f] = 0.f;
    }

    auto stage = [&](int chunk, int bf) {
        unsigned sx = smem_u + 4u * (bf ? XA1 : XA0);
        unsigned sw = smem_u + 4u * (bf ? WA1 : WA0);
        const __half* xs = g_xr + (size_t)(b * 8 + chunk) * 65536;
        for (int idx = tid; idx < 768; idx += 256) {
            int row = idx >> 7, f4 = idx & 127;   // f4: 16B piece within row (64px*32B)
            int ih = 4 * hb - 1 + row;
            bool v = ((unsigned)ih < 64u);
            cp16(sx + (unsigned)(row * 2112 + 32 + f4 * 16),
                 xs + (size_t)(v ? ih : 0) * 1024 + f4 * 8, v ? 16 : 0);
        }
        const __half* ws = g_wr + (size_t)(e * 8 + chunk) * 18432;
        for (int idx = tid; idx < 2304; idx += 256)
            cp16(sw + idx * 16u, ws + idx * 8, 16);
    };

    stage(0, 0); cp_commit();
    stage(1, 1); cp_commit();

    for (int c = 0; c < 8; c++) {
        cp_wait1();
        __syncthreads();
        int bf = c & 1;
        const char* sX = (const char*)smem_all + 4 * (bf ? XA1 : XA0);
        const char* sW = (const char*)smem_all + 4 * (bf ? WA1 : WA0);
#pragma unroll
        for (int tap = 0; tap < 9; tap++) {
            int dy = tap / 3, dx = tap - dy * 3;
            const char* wp = sW + tap * 4096 + (ocw * 64 + q) * 32 + r * 8;
            uint2 Alo[4], Ahi[4];
#pragma unroll
            for (int mt = 0; mt < 4; mt++) {
                Alo[mt] = *(const uint2*)(wp + mt * 512);        // row q  : a0,a2
                Ahi[mt] = *(const uint2*)(wp + mt * 512 + 256);  // row q+8: a1,a3
            }
            const char* xp = sX + (orow + dy) * 2112 + (q + dx) * 32 + r * 8;
#pragma unroll
            for (int nt = 0; nt < 8; nt++) {
                uint2 Bv = *(const uint2*)(xp + nt * 256);
#pragma unroll
                for (int mt = 0; mt < 4; mt++)
                    mma16(acc[mt][nt], Alo[mt].x, Ahi[mt].x, Alo[mt].y, Ahi[mt].y,
                          Bv.x, Bv.y);
            }
        }
        __syncthreads();
        if (c + 2 < 8) stage(c + 2, bf);
        cp_commit();
    }

    // ---- stats: one 16-oc group per m-tile ----
#pragma unroll
    for (int mt = 0; mt < 4; mt++) {
        float s1 = 0.f, s2 = 0.f;
#pragma unroll
        for (int nt = 0; nt < 8; nt++)
#pragma unroll
            for (int j = 0; j < 4; j++) {
                float v = acc[mt][nt][j];
                s1 += v; s2 += v * v;
            }
#pragma unroll
        for (int off = 16; off > 0; off >>= 1) {
            s1 += __shfl_xor_sync(0xffffffffu, s1, off);
            s2 += __shfl_xor_sync(0xffffffffu, s2, off);
        }
        if (lane == 0) {
            int g = ocw * 4 + mt;
            int slot = (e * NB + b) * 8 + g;
            g_part_exp[(slot * 64 + hb * 4 + orow) * 2 + 0] = s1;
            g_part_exp[(slot * 64 + hb * 4 + orow) * 2 + 1] = s2;
        }
    }

    // ---- output: two staging passes of 128 oc x 128 px, store fp16 ----
    float* stg = smem_all;
    size_t zbase = (size_t)((e * NB + b) * NC) * HWSZ;
#pragma unroll
    for (int p = 0; p < 2; p++) {
        __syncthreads();
        if ((orow >> 1) == p) {
#pragma unroll
            for (int mt = 0; mt < 4; mt++)
#pragma unroll
                for (int nt = 0; nt < 8; nt++)
#pragma unroll
                    for (int j = 0; j < 4; j++) {
                        int oc = ocw * 64 + mt * 16 + q + 8 * (j >> 1);
                        int px = (orow & 1) * 64 + nt * 8 + 2 * r + (j & 1);
                        stg[oc * 132 + px] = acc[mt][nt][j];
                    }
        }
        __syncthreads();
        for (int idx = tid; idx < 4096; idx += 256) {
            int oc = idx >> 5, p4 = (idx & 31) * 4;
            float4 v = *(const float4*)(stg + oc * 132 + p4);
            int h = 4 * hb + 2 * p + (p4 >> 6), w = p4 & 63;
            __half2* dst = (__half2*)(g_z + zbase + (size_t)oc * HWSZ + h * 64 + w);
            dst[0] = __floats2half2_rn(v.x, v.y);
            dst[1] = __floats2half2_rn(v.z, v.w);
        }
    }
}

// ---------------- finalize stats ----------------
__global__ void k_finalize(int which) {
    const float* part; float* ms; int nper, nslots; float invN;
    if (which == 0)      { part = g_part_exp; ms = g_ms_exp; nper = 64; nslots = 1024; invN = 1.0f / 65536.0f; }
    else if (which == 1) { part = g_part1;    ms = g_ms1;    nper = 32; nslots = 128;  invN = 1.0f / 262144.0f; }
    else if (which == 2) { part = g_part2;    ms = g_ms2;    nper = 64; nslots = 128;  invN = 1.0f / 262144.0f; }
    else                 { part = g_part3;    ms = g_ms3;    nper = 16; nslots = 128;  invN = 1.0f / 16384.0f; }
    int s = blockIdx.x * blockDim.x + threadIdx.x;
    if (s >= nslots) return;
    float s1 = 0.f, s2 = 0.f;
    for (int i = 0; i < nper; i++) {
        s1 += part[(s * nper + i) * 2 + 0];
        s2 += part[(s * nper + i) * 2 + 1];
    }
    float m = s1 * invN;
    float v = s2 * invN - m * m;
    ms[s * 2 + 0] = m;
    ms[s * 2 + 1] = rsqrtf(v + 1e-5f);
}

// ---------------- combine: GN+SiLU+residual+weights -> fp16 permuted --------
__global__ __launch_bounds__(256) void k_combine(const float* __restrict__ x,
                                                 const float* __restrict__ gs,
                                                 const float* __restrict__ gb) {
    int idx = blockIdx.x * 256 + threadIdx.x;   // 524288 = B*8*4096
    int px = idx & 4095, chunk = (idx >> 12) & 7, b = idx >> 15;
    int h = px >> 6, w = px & 63;
    int patch = ((h >> 4) << 2) + (w >> 4);
    float res[16];
#pragma unroll
    for (int j = 0; j < 16; j++) {
        int c = chunk * 16 + kmap(j);
        res[j] = x[((b * 128 + c) << 12) + px];
    }
#pragma unroll
    for (int e = 0; e < 8; e++) {
        float m  = g_ms_exp[(((e * NB + b) * 8) + chunk) * 2 + 0];
        float rs = g_ms_exp[(((e * NB + b) * 8) + chunk) * 2 + 1];
        float wt = g_wts[patch * 8 + e];
#pragma unroll
        for (int j = 0; j < 16; j++) {
            int c = chunk * 16 + kmap(j);
            float zv = __half2float(g_z[((size_t)((e * NB + b) * NC + c)) * HWSZ + px]);
            float t = (zv - m) * rs * gs[e * NC + c] + gb[e * NC + c];
            res[j] += wt * silu_f(t);
        }
    }
    __half2* dst = (__half2*)(g_combp + (size_t)idx * 16);
#pragma unroll
    for (int j = 0; j < 8; j++)
        dst[j] = __floats2half2_rn(res[2 * j], res[2 * j + 1]);
}

// ---------------- pw1: fp16 mma, block 128hc x 128px, K = 8 chunks x 16 -----
#define P1X0 0
#define P1W0 1024
#define P1X1 2048
#define P1W1 3072
#define RED1 16896
#define PW1F 16928

__global__ __launch_bounds__(256, 2) void k_pw1_mma() {
    int tid = threadIdx.x;
    int wid = tid >> 5, lane = tid & 31;
    int q = lane >> 2, r = lane & 3;
    int ocw = wid >> 1, ph = wid & 1;
    int ht = blockIdx.x, pt = blockIdx.y, b = blockIdx.z;
    unsigned smem_u = (unsigned)__cvta_generic_to_shared(smem_all);

    float acc[2][8][4];
#pragma unroll
    for (int i = 0; i < 2; i++)
#pragma unroll
        for (int j = 0; j < 8; j++)
#pragma unroll
            for (int l = 0; l < 4; l++) acc[i][j][l] = 0.f;

    auto stage = [&](int chunk, int bf) {
        unsigned sxa = smem_u + 4u * (bf ? P1X1 : P1X0);
        unsigned swa = smem_u + 4u * (bf ? P1W1 : P1W0);
        const __half* xsrc = g_combp + ((size_t)(b * 8 + chunk) * 4096 + pt * 128) * 16;
        const __half* wsrc = g_w1r + (ht * 8 + chunk) * 2048;
        cp16(sxa + tid * 16u, xsrc + tid * 8, 16);
        cp16(swa + tid * 16u, wsrc + tid * 8, 16);
    };

    stage(0, 0); cp_commit();
    stage(1, 1); cp_commit();

    for (int k = 0; k < 8; k++) {
        cp_wait1();
        __syncthreads();
        int bf = k & 1;
        const char* sX = (const char*)smem_all + 4 * (bf ? P1X1 : P1X0);
        const char* sW = (const char*)smem_all + 4 * (bf ? P1W1 : P1W0);
        const char* wp = sW + (ocw * 32 + q) * 32 + r * 8;
        uint2 Alo[2], Ahi[2];
#pragma unroll
        for (int mt = 0; mt < 2; mt++) {
            Alo[mt] = *(const uint2*)(wp + mt * 512);
            Ahi[mt] = *(const uint2*)(wp + mt * 512 + 256);
        }
#pragma unroll
        for (int nt = 0; nt < 8; nt++) {
            const char* xp = sX + (ph * 64 + nt * 8 + q) * 32 + r * 8;
            uint2 Bv = *(const uint2*)(xp);
            mma16(acc[0][nt], Alo[0].x, Ahi[0].x, Alo[0].y, Ahi[0].y, Bv.x, Bv.y);
            mma16(acc[1][nt], Alo[1].x, Ahi[1].x, Alo[1].y, Ahi[1].y, Bv.x, Bv.y);
        }
        __syncthreads();
        if (k + 2 < 8) stage(k + 2, bf);
        cp_commit();
    }

    float s1 = 0.f, s2 = 0.f;
#pragma unroll
    for (int i = 0; i < 2; i++)
#pragma unroll
        for (int j = 0; j < 8; j++)
#pragma unroll
            for (int l = 0; l < 4; l++) {
                float v = acc[i][j][l];
                s1 += v; s2 += v * v;
            }
#pragma unroll
    for (int off = 16; off > 0; off >>= 1) {
        s1 += __shfl_xor_sync(0xffffffffu, s1, off);
        s2 += __shfl_xor_sync(0xffffffffu, s2, off);
    }
    float* red = smem_all + RED1;
    if (lane == 0) { red[wid * 2] = s1; red[wid * 2 + 1] = s2; }

    float* stg = smem_all;
#pragma unroll
    for (int mt = 0; mt < 2; mt++)
#pragma unroll
        for (int nt = 0; nt < 8; nt++)
#pragma unroll
            for (int j = 0; j < 4; j++) {
                int hcl = ocw * 32 + mt * 16 + q + 8 * (j >> 1);
                int w = nt * 8 + 2 * r + (j & 1);
                stg[hcl * 132 + ph * 64 + w] = acc[mt][nt][j];
            }
    __syncthreads();
    if (tid < 2) {
        float a = red[tid * 8 + 0] + red[tid * 8 + 2] + red[tid * 8 + 4] + red[tid * 8 + 6];
        float bq = red[tid * 8 + 1] + red[tid * 8 + 3] + red[tid * 8 + 5] + red[tid * 8 + 7];
        int slot = b * 8 + ht * 2 + tid;
        g_part1[(slot * 32 + pt) * 2 + 0] = a;
        g_part1[(slot * 32 + pt) * 2 + 1] = bq;
    }
    for (int idx = tid; idx < 4096; idx += 256) {
        int hcl = idx >> 5, p4 = (idx & 31) * 4;
        float4 v = *(const float4*)(stg + hcl * 132 + p4);
        *(float4*)(g_h1 + (size_t)(b * NHC + ht * 128 + hcl) * HWSZ + pt * 128 + p4) = v;
    }
}

// ---------------- dw: one block per (channel, b); compact stride-2 output ---
__global__ __launch_bounds__(256) void k_dw(const float* __restrict__ w_dw,
                                            const float* __restrict__ s1v,
                                            const float* __restrict__ b1v) {
    __shared__ float sa[4356];
    __shared__ float red[512];
    int tid = threadIdx.x;
    int ch = blockIdx.x, b = blockIdx.y;
    float m  = g_ms1[(b * 8 + (ch >> 6)) * 2 + 0];
    float rs = g_ms1[(b * 8 + (ch >> 6)) * 2 + 1];
    float sc = s1v[ch], bi = b1v[ch];
    for (int idx = tid; idx < 4356; idx += 256) sa[idx] = 0.f;
    __syncthreads();
    const float* src = g_h1 + (size_t)(b * NHC + ch) * 4096;
    for (int idx = tid; idx < 1024; idx += 256) {
        int r = idx >> 4, w4 = (idx & 15) * 4;
        float4 v = *(const float4*)(src + r * 64 + w4);
        float* d = sa + (r + 1) * 66 + 1 + w4;
        d[0] = silu_f((v.x - m) * rs * sc + bi);
        d[1] = silu_f((v.y - m) * rs * sc + bi);
        d[2] = silu_f((v.z - m) * rs * sc + bi);
        d[3] = silu_f((v.w - m) * rs * sc + bi);
    }
    __syncthreads();
    float wd[9];
#pragma unroll
    for (int j = 0; j < 9; j++) wd[j] = w_dw[ch * 9 + j];
    int r = tid >> 2, w0 = (tid & 3) * 16;
    float s1 = 0.f, s2 = 0.f;
    float* orow = g_h2 + (size_t)(b * NHC + ch) * 1024 + (r >> 1) * 32;
    bool reven = (r & 1) == 0;
#pragma unroll
    for (int k = 0; k < 16; k++) {
        int w = w0 + k;
        float a = 0.f;
#pragma unroll
        for (int dr = 0; dr < 3; dr++)
#pragma unroll
            for (int dt = 0; dt < 3; dt++)
                a += sa[(r + dr) * 66 + w + dt] * wd[dr * 3 + dt];
        s1 += a; s2 += a * a;
        if (reven && !(w & 1)) orow[w >> 1] = a;
    }
    red[tid] = s1; red[256 + tid] = s2;
    __syncthreads();
    for (int st = 128; st > 0; st >>= 1) {
        if (tid < st) { red[tid] += red[tid + st]; red[256 + tid] += red[256 + tid + st]; }
        __syncthreads();
    }
    if (tid == 0) {
        int slot = b * 8 + (ch >> 6);
        g_part2[(slot * 64 + (ch & 63)) * 2 + 0] = red[0];
        g_part2[(slot * 64 + (ch & 63)) * 2 + 1] = red[256];
    }
}

// ---------------- pw2 (reads compact h2) ----------------
__global__ __launch_bounds__(256) void k_pw2(const float* __restrict__ w_pw2,
                                             const float* __restrict__ s2v,
                                             const float* __restrict__ b2v) {
    __shared__ float sA[2048], sW[4096], red[512];
    int tid = threadIdx.x;
    int pt = blockIdx.x, b = blockIdx.y;
    int pg = tid & 15, og = tid >> 4;
    float acc[32];
#pragma unroll
    for (int i = 0; i < 32; i++) acc[i] = 0.f;

    for (int c0 = 0; c0 < 512; c0 += 32) {
        __syncthreads();
        for (int idx = tid; idx < 2048; idx += 256) {
            int kc = idx >> 6, p = idx & 63;
            int hc = c0 + kc;
            float v = g_h2[(size_t)(b * NHC + hc) * 1024 + pt * 64 + p];
            float m  = g_ms2[(b * 8 + (hc >> 6)) * 2 + 0];
            float rr = g_ms2[(b * 8 + (hc >> 6)) * 2 + 1];
            float t = (v - m) * rr * s2v[hc] + b2v[hc];
            sA[idx] = silu_f(t);
        }
        for (int idx = tid; idx < 4096; idx += 256) {
            int kc = idx >> 7, co = idx & 127;
            sW[idx] = w_pw2[co * NHC + c0 + kc];
        }
        __syncthreads();
        for (int kc = 0; kc < 32; kc++) {
            float a0 = sA[kc * 64 + 4 * pg + 0];
            float a1 = sA[kc * 64 + 4 * pg + 1];
            float a2 = sA[kc * 64 + 4 * pg + 2];
            float a3 = sA[kc * 64 + 4 * pg + 3];
#pragma unroll
            for (int l = 0; l < 8; l++) {
                float wv = sW[kc * 128 + 8 * og + l];
                acc[0 * 8 + l] += a0 * wv;
                acc[1 * 8 + l] += a1 * wv;
                acc[2 * 8 + l] += a2 * wv;
                acc[3 * 8 + l] += a3 * wv;
            }
        }
    }
    float s1 = 0.f, s2 = 0.f;
#pragma unroll
    for (int i = 0; i < 32; i++) { s1 += acc[i]; s2 += acc[i] * acc[i]; }
    red[tid] = s1; red[256 + tid] = s2;
    __syncthreads();
    if ((tid & 31) == 0) {
        float a = 0.f, bq = 0.f;
        for (int i = 0; i < 32; i++) { a += red[tid + i]; bq += red[256 + tid + i]; }
        int g = tid >> 5;
        g_part3[((b * 8 + g) * 16 + pt) * 2 + 0] = a;
        g_part3[((b * 8 + g) * 16 + pt) * 2 + 1] = bq;
    }
#pragma unroll
    for (int k = 0; k < 4; k++) {
        int pi = pt * 64 + 4 * pg + k;
        int ii = pi >> 5, jj = pi & 31;
#pragma unroll
        for (int l = 0; l < 8; l++) {
            int co = 8 * og + l;
            g_h3[((b * NC + co) << 10) + (ii << 5) + jj] = acc[k * 8 + l];
        }
    }
}

// ---------------- final ----------------
__global__ void k_out(float* __restrict__ out,
                      const float* __restrict__ s3v, const float* __restrict__ b3v) {
    int idx = blockIdx.x * 256 + threadIdx.x;
    int co = (idx >> 10) & 127, b = idx >> 17;
    int g = co >> 4;
    float m  = g_ms3[(b * 8 + g) * 2 + 0];
    float rs = g_ms3[(b * 8 + g) * 2 + 1];
    float t = (g_h3[idx] - m) * rs * s3v[co] + b3v[co];
    out[idx] = silu_f(t);
}

// ---------------- launch ----------------
extern "C" void kernel_launch(void* const* d_in, const int* in_sizes, int n_in,
                              void* d_out, int out_size) {
    const float* x      = (const float*)d_in[0];
    const float* w_exp  = (const float*)d_in[1];
    const float* gs_e   = (const float*)d_in[2];
    const float* gb_e   = (const float*)d_in[3];
    const float* w1     = (const float*)d_in[4];
    const float* b1     = (const float*)d_in[5];
    const float* w2     = (const float*)d_in[6];
    const float* b2     = (const float*)d_in[7];
    const float* w_pw1  = (const float*)d_in[8];
    const float* gn1_s  = (const float*)d_in[9];
    const float* gn1_b  = (const float*)d_in[10];
    const float* w_dw   = (const float*)d_in[11];
    const float* gn2_s  = (const float*)d_in[12];
    const float* gn2_b  = (const float*)d_in[13];
    const float* w_pw2  = (const float*)d_in[14];
    const float* gn3_s  = (const float*)d_in[15];
    const float* gn3_b  = (const float*)d_in[16];
    float* out = (float*)d_out;

    static bool attr_done = false;
    if (!attr_done) {
        cudaFuncSetAttribute(k_expert_mma, cudaFuncAttributeMaxDynamicSharedMemorySize,
                             EXPF * 4);
        cudaFuncSetAttribute(k_pw1_mma, cudaFuncAttributeMaxDynamicSharedMemorySize,
                             PW1F * 4);
        attr_done = true;
    }

    k_xform_x<<<2048, 256>>>(x);
    k_xform_w<<<288, 256>>>(w_exp);
    k_xform_w1<<<16, 256>>>(w_pw1);
    k_router<<<1, 1024>>>(w1, b1, w2, b2);
    k_expert_mma<<<dim3(16, 128), 256, EXPF * 4>>>();
    k_finalize<<<4, 256>>>(0);
    k_combine<<<2048, 256>>>(x, gs_e, gb_e);
    k_pw1_mma<<<dim3(4, 32, 16), 256, PW1F * 4>>>();
    k_finalize<<<4, 256>>>(1);
    k_dw<<<dim3(512, 16), 256>>>(w_dw, gn1_s, gn1_b);
    k_finalize<<<4, 256>>>(2);
    k_pw2<<<dim3(16, 16), 256>>>(w_pw2, gn2_s, gn2_b);
    k_finalize<<<4, 256>>>(3);
    k_out<<<8192, 256>>>(out, gn3_s, gn3_b);
}

// round 8
// speedup vs baseline: 6.5198x; 1.0464x over previous
#include <cuda_runtime.h>
#include <cuda_fp16.h>
#include <math.h>

// ---------------- problem constants ----------------
#define NB   16
#define NC   128
#define NHC  512
#define HWSZ 4096

// ---------------- scratch ----------------
__device__ __half g_z[67108864];     // [E*B][C][HW] expert conv raw (fp16)
__device__ __half g_combp[8388608];  // [B][chunk8][px4096][16kp] fp16
__device__ __half g_h1[33554432];    // fp16 now
__device__ float  g_h2[8388608];     // COMPACT [B][HC][32][32]
__device__ float  g_h3[2097152];
__device__ float  g_wts[128];
__device__ __half g_xr[8388608];     // [B][chunk8][h][w][16kp]
__device__ __half g_wr[1179648];     // [E][chunk8][tap9][oc128][16kp]
__device__ __half g_w1r[65536];      // [ht4][chunk8][hcl128][16kp]
__device__ float g_part_exp[1024 * 64 * 2];
__device__ float g_ms_exp[1024 * 2];
__device__ float g_part1[128 * 32 * 2];
__device__ float g_ms1[128 * 2];
__device__ float g_part2[128 * 64 * 2];
__device__ float g_ms2[128 * 2];
__device__ float g_part3[128 * 16 * 2];
__device__ float g_ms3[128 * 2];

__device__ __forceinline__ float silu_f(float x) {
    return x / (1.0f + __expf(-x));
}
// permuted k index: j in [0,16) -> k, so thread r's 4 contiguous halves are
// k = {2r, 2r+1, 2r+8, 2r+9}
__device__ __forceinline__ int kmap(int j) {
    return ((j >> 2) * 2) + (j & 1) + ((j >> 1) & 1) * 8;
}
__device__ __forceinline__ void cp16(unsigned s, const void* g, int sz) {
    asm volatile("cp.async.cg.shared.global [%0], [%1], 16, %2;\n"
                 :: "r"(s), "l"(g), "r"(sz) : "memory");
}
__device__ __forceinline__ void cp_commit() {
    asm volatile("cp.async.commit_group;\n" ::: "memory");
}
__device__ __forceinline__ void cp_wait1() {
    asm volatile("cp.async.wait_group 1;\n" ::: "memory");
}
__device__ __forceinline__ void mma16(float* c, unsigned a0, unsigned a1, unsigned a2,
                                      unsigned a3, unsigned b0, unsigned b1) {
    asm volatile("mma.sync.aligned.m16n8k16.row.col.f32.f16.f16.f32 "
                 "{%0,%1,%2,%3}, {%4,%5,%6,%7}, {%8,%9}, {%0,%1,%2,%3};"
                 : "+f"(c[0]), "+f"(c[1]), "+f"(c[2]), "+f"(c[3])
                 : "r"(a0), "r"(a1), "r"(a2), "r"(a3), "r"(b0), "r"(b1));
}

// ---------------- transforms (fp16 + permute) ----------
__global__ void k_xform_x(const float* __restrict__ x) {
    int idx = blockIdx.x * 256 + threadIdx.x;   // 524288
    int w = idx & 63, h = (idx >> 6) & 63, chunk = (idx >> 12) & 7, b = idx >> 15;
    __align__(16) __half o[16];
#pragma unroll
    for (int j = 0; j < 16; j++) {
        int c = chunk * 16 + kmap(j);
        o[j] = __float2half(x[((b * 128 + c) << 12) + (h << 6) + w]);
    }
    uint4* dst = (uint4*)(g_xr + (size_t)idx * 16);
    dst[0] = ((uint4*)o)[0];
    dst[1] = ((uint4*)o)[1];
}

__global__ void k_xform_w(const float* __restrict__ w_exp) {
    int idx = blockIdx.x * 256 + threadIdx.x;   // 73728
    int oc = idx & 127;
    int t2 = idx >> 7;
    int tap = t2 % 9, ec = t2 / 9;
    int chunk = ec & 7, e = ec >> 3;
    __align__(16) __half o[16];
#pragma unroll
    for (int j = 0; j < 16; j++) {
        int c = chunk * 16 + kmap(j);
        o[j] = __float2half(w_exp[((e * 128 + oc) * 128 + c) * 9 + tap]);
    }
    uint4* dst = (uint4*)(g_wr + (size_t)idx * 16);
    dst[0] = ((uint4*)o)[0];
    dst[1] = ((uint4*)o)[1];
}

__global__ void k_xform_w1(const float* __restrict__ w_pw1) {
    int idx = blockIdx.x * 256 + threadIdx.x;   // 4096
    int hcl = idx & 127, chunk = (idx >> 7) & 7, ht = idx >> 10;
    __align__(16) __half o[16];
#pragma unroll
    for (int j = 0; j < 16; j++) {
        int c = chunk * 16 + kmap(j);
        o[j] = __float2half(w_pw1[(ht * 128 + hcl) * 128 + c]);
    }
    uint4* dst = (uint4*)(g_w1r + (size_t)idx * 16);
    dst[0] = ((uint4*)o)[0];
    dst[1] = ((uint4*)o)[1];
}

// ---------------- router ----------------
__global__ void k_router(const float* __restrict__ w1, const float* __restrict__ b1,
                         const float* __restrict__ w2, const float* __restrict__ b2) {
    __shared__ float feats[16 * 32];
    __shared__ float hid[16 * 64];
    __shared__ float lg[16 * 8];
    int tid = threadIdx.x;
    if (tid < 512) {
        int p = tid >> 5, f = tid & 31;
        int py = p >> 2, px = p & 3;
        int k = f & 7, kind = f >> 3;
        float freq = exp2f((float)k) * 3.14159265358979323846f;
        float cy = (py + 0.5f) * 0.25f;
        float cx = (px + 0.5f) * 0.25f;
        float v;
        if (kind == 0)      v = sinf(cy * freq);
        else if (kind == 1) v = cosf(cy * freq);
        else if (kind == 2) v = sinf(cx * freq);
        else                v = cosf(cx * freq);
        feats[p * 32 + f] = v;
    }
    __syncthreads();
    {
        int p = tid >> 6, hh = tid & 63;
        float a = b1[hh];
        for (int f = 0; f < 32; f++) a += feats[p * 32 + f] * w1[f * 64 + hh];
        hid[p * 64 + hh] = a / (1.0f + expf(-a));
    }
    __syncthreads();
    if (tid < 128) {
        int p = tid >> 3, e = tid & 7;
        float a = b2[e];
        for (int hh = 0; hh < 64; hh++) a += hid[p * 64 + hh] * w2[hh * 8 + e];
        lg[p * 8 + e] = a;
    }
    __syncthreads();
    if (tid < 16) {
        float mx = -1e30f;
        for (int e = 0; e < 8; e++) mx = fmaxf(mx, lg[tid * 8 + e]);
        float ex[8], s = 0.f;
        for (int e = 0; e < 8; e++) { ex[e] = expf(lg[tid * 8 + e] - mx); s += ex[e]; }
        float inv = 1.0f / s;
        for (int e = 0; e < 8; e++) g_wts[tid * 8 + e] = ex[e] * inv;
    }
}

// ---------------- expert conv: fp16 mma m16n8k16, block 128oc x 256px -------
// 8 warps = ocw(2: 64oc) x orow(4). grid (hb=16, e*16+b=128). K = 8 chunks x 16c.
#define XA0 0
#define XA1 3168
#define WA0 6336
#define WA1 15552
#define EXPF 24768

extern __shared__ float smem_all[];

__global__ __launch_bounds__(256, 1) void k_expert_mma() {
    int tid = threadIdx.x;
    int wid = tid >> 5, lane = tid & 31;
    int q = lane >> 2, r = lane & 3;
    int ocw = wid & 1, orow = wid >> 1;
    int hb = blockIdx.x;
    int b = blockIdx.y & 15, e = blockIdx.y >> 4;
    unsigned smem_u = (unsigned)__cvta_generic_to_shared(smem_all);

    float acc[4][8][4];
#pragma unroll
    for (int i = 0; i < 4; i++)
#pragma unroll
        for (int j = 0; j < 8; j++)
#pragma unroll
            for (int l = 0; l < 4; l++) acc[i][j][l] = 0.f;

    // zero halo pixels (px 0 and 65) of both X buffers: 32B each, as 8 floats
    if (tid < 192) {
        int bf = tid / 96, t = tid % 96;
        int row = t >> 4, side = (t >> 3) & 1, f = t & 7;
        smem_all[(bf ? XA1 : XA0) + row * 528 + (side ? 65 : 0) * 8 + f] = 0.f;
    }

    auto stage = [&](int chunk, int bf) {
        unsigned sx = smem_u + 4u * (bf ? XA1 : XA0);
        unsigned sw = smem_u + 4u * (bf ? WA1 : WA0);
        const __half* xs = g_xr + (size_t)(b * 8 + chunk) * 65536;
        for (int idx = tid; idx < 768; idx += 256) {
            int row = idx >> 7, f4 = idx & 127;
            int ih = 4 * hb - 1 + row;
            bool v = ((unsigned)ih < 64u);
            cp16(sx + (unsigned)(row * 2112 + 32 + f4 * 16),
                 xs + (size_t)(v ? ih : 0) * 1024 + f4 * 8, v ? 16 : 0);
        }
        const __half* ws = g_wr + (size_t)(e * 8 + chunk) * 18432;
        for (int idx = tid; idx < 2304; idx += 256)
            cp16(sw + idx * 16u, ws + idx * 8, 16);
    };

    stage(0, 0); cp_commit();
    stage(1, 1); cp_commit();

    for (int c = 0; c < 8; c++) {
        cp_wait1();
        __syncthreads();
        int bf = c & 1;
        const char* sX = (const char*)smem_all + 4 * (bf ? XA1 : XA0);
        const char* sW = (const char*)smem_all + 4 * (bf ? WA1 : WA0);
#pragma unroll
        for (int tap = 0; tap < 9; tap++) {
            int dy = tap / 3, dx = tap - dy * 3;
            const char* wp = sW + tap * 4096 + (ocw * 64 + q) * 32 + r * 8;
            uint2 Alo[4], Ahi[4];
#pragma unroll
            for (int mt = 0; mt < 4; mt++) {
                Alo[mt] = *(const uint2*)(wp + mt * 512);
                Ahi[mt] = *(const uint2*)(wp + mt * 512 + 256);
            }
            const char* xp = sX + (orow + dy) * 2112 + (q + dx) * 32 + r * 8;
#pragma unroll
            for (int nt = 0; nt < 8; nt++) {
                uint2 Bv = *(const uint2*)(xp + nt * 256);
#pragma unroll
                for (int mt = 0; mt < 4; mt++)
                    mma16(acc[mt][nt], Alo[mt].x, Ahi[mt].x, Alo[mt].y, Ahi[mt].y,
                          Bv.x, Bv.y);
            }
        }
        __syncthreads();
        if (c + 2 < 8) stage(c + 2, bf);
        cp_commit();
    }

    // ---- stats: one 16-oc group per m-tile ----
#pragma unroll
    for (int mt = 0; mt < 4; mt++) {
        float s1 = 0.f, s2 = 0.f;
#pragma unroll
        for (int nt = 0; nt < 8; nt++)
#pragma unroll
            for (int j = 0; j < 4; j++) {
                float v = acc[mt][nt][j];
                s1 += v; s2 += v * v;
            }
#pragma unroll
        for (int off = 16; off > 0; off >>= 1) {
            s1 += __shfl_xor_sync(0xffffffffu, s1, off);
            s2 += __shfl_xor_sync(0xffffffffu, s2, off);
        }
        if (lane == 0) {
            int g = ocw * 4 + mt;
            int slot = (e * NB + b) * 8 + g;
            g_part_exp[(slot * 64 + hb * 4 + orow) * 2 + 0] = s1;
            g_part_exp[(slot * 64 + hb * 4 + orow) * 2 + 1] = s2;
        }
    }

    // ---- output: single fp16 staging pass (128 oc x 256 px, pitch 264) ----
    __half* stg = (__half*)smem_all;
#pragma unroll
    for (int mt = 0; mt < 4; mt++)
#pragma unroll
        for (int nt = 0; nt < 8; nt++) {
            int oc0 = ocw * 64 + mt * 16 + q;
            int px = orow * 64 + nt * 8 + 2 * r;
            *(__half2*)(stg + oc0 * 264 + px) =
                __floats2half2_rn(acc[mt][nt][0], acc[mt][nt][1]);
            *(__half2*)(stg + (oc0 + 8) * 264 + px) =
                __floats2half2_rn(acc[mt][nt][2], acc[mt][nt][3]);
        }
    __syncthreads();
    size_t zbase = (size_t)((e * NB + b) * NC) * HWSZ;
    for (int idx = tid; idx < 4096; idx += 256) {
        int oc = idx >> 5, p8 = (idx & 31) * 8;
        uint4 v = *(const uint4*)(stg + oc * 264 + p8);
        int h = 4 * hb + (p8 >> 6), w = p8 & 63;
        *(uint4*)(g_z + zbase + (size_t)oc * HWSZ + h * 64 + w) = v;
    }
}

// ---------------- finalize stats ----------------
__global__ void k_finalize(int which) {
    const float* part; float* ms; int nper, nslots; float invN;
    if (which == 0)      { part = g_part_exp; ms = g_ms_exp; nper = 64; nslots = 1024; invN = 1.0f / 65536.0f; }
    else if (which == 1) { part = g_part1;    ms = g_ms1;    nper = 32; nslots = 128;  invN = 1.0f / 262144.0f; }
    else if (which == 2) { part = g_part2;    ms = g_ms2;    nper = 64; nslots = 128;  invN = 1.0f / 262144.0f; }
    else                 { part = g_part3;    ms = g_ms3;    nper = 16; nslots = 128;  invN = 1.0f / 16384.0f; }
    int s = blockIdx.x * blockDim.x + threadIdx.x;
    if (s >= nslots) return;
    float s1 = 0.f, s2 = 0.f;
    for (int i = 0; i < nper; i++) {
        s1 += part[(s * nper + i) * 2 + 0];
        s2 += part[(s * nper + i) * 2 + 1];
    }
    float m = s1 * invN;
    float v = s2 * invN - m * m;
    ms[s * 2 + 0] = m;
    ms[s * 2 + 1] = rsqrtf(v + 1e-5f);
}

// ---------------- combine: GN+SiLU+residual+weights -> fp16 permuted --------
__global__ __launch_bounds__(256) void k_combine(const float* __restrict__ x,
                                                 const float* __restrict__ gs,
                                                 const float* __restrict__ gb) {
    int idx = blockIdx.x * 256 + threadIdx.x;   // 524288 = B*8*4096
    int px = idx & 4095, chunk = (idx >> 12) & 7, b = idx >> 15;
    int h = px >> 6, w = px & 63;
    int patch = ((h >> 4) << 2) + (w >> 4);
    float res[16];
#pragma unroll
    for (int j = 0; j < 16; j++) {
        int c = chunk * 16 + kmap(j);
        res[j] = x[((b * 128 + c) << 12) + px];
    }
#pragma unroll
    for (int e = 0; e < 8; e++) {
        float m  = g_ms_exp[(((e * NB + b) * 8) + chunk) * 2 + 0];
        float rs = g_ms_exp[(((e * NB + b) * 8) + chunk) * 2 + 1];
        float wt = g_wts[patch * 8 + e];
#pragma unroll
        for (int j = 0; j < 16; j++) {
            int c = chunk * 16 + kmap(j);
            float zv = __half2float(g_z[((size_t)((e * NB + b) * NC + c)) * HWSZ + px]);
            float t = (zv - m) * rs * gs[e * NC + c] + gb[e * NC + c];
            res[j] += wt * silu_f(t);
        }
    }
    __half2* dst = (__half2*)(g_combp + (size_t)idx * 16);
#pragma unroll
    for (int j = 0; j < 8; j++)
        dst[j] = __floats2half2_rn(res[2 * j], res[2 * j + 1]);
}

// ---------------- pw1: fp16 mma, block 128hc x 128px ----------------
#define P1X0 0
#define P1W0 1024
#define P1X1 2048
#define P1W1 3072
#define RED1 16896
#define PW1F 16928

__global__ __launch_bounds__(256, 2) void k_pw1_mma() {
    int tid = threadIdx.x;
    int wid = tid >> 5, lane = tid & 31;
    int q = lane >> 2, r = lane & 3;
    int ocw = wid >> 1, ph = wid & 1;
    int ht = blockIdx.x, pt = blockIdx.y, b = blockIdx.z;
    unsigned smem_u = (unsigned)__cvta_generic_to_shared(smem_all);

    float acc[2][8][4];
#pragma unroll
    for (int i = 0; i < 2; i++)
#pragma unroll
        for (int j = 0; j < 8; j++)
#pragma unroll
            for (int l = 0; l < 4; l++) acc[i][j][l] = 0.f;

    auto stage = [&](int chunk, int bf) {
        unsigned sxa = smem_u + 4u * (bf ? P1X1 : P1X0);
        unsigned swa = smem_u + 4u * (bf ? P1W1 : P1W0);
        const __half* xsrc = g_combp + ((size_t)(b * 8 + chunk) * 4096 + pt * 128) * 16;
        const __half* wsrc = g_w1r + (ht * 8 + chunk) * 2048;
        cp16(sxa + tid * 16u, xsrc + tid * 8, 16);
        cp16(swa + tid * 16u, wsrc + tid * 8, 16);
    };

    stage(0, 0); cp_commit();
    stage(1, 1); cp_commit();

    for (int k = 0; k < 8; k++) {
        cp_wait1();
        __syncthreads();
        int bf = k & 1;
        const char* sX = (const char*)smem_all + 4 * (bf ? P1X1 : P1X0);
        const char* sW = (const char*)smem_all + 4 * (bf ? P1W1 : P1W0);
        const char* wp = sW + (ocw * 32 + q) * 32 + r * 8;
        uint2 Alo[2], Ahi[2];
#pragma unroll
        for (int mt = 0; mt < 2; mt++) {
            Alo[mt] = *(const uint2*)(wp + mt * 512);
            Ahi[mt] = *(const uint2*)(wp + mt * 512 + 256);
        }
#pragma unroll
        for (int nt = 0; nt < 8; nt++) {
            const char* xp = sX + (ph * 64 + nt * 8 + q) * 32 + r * 8;
            uint2 Bv = *(const uint2*)(xp);
            mma16(acc[0][nt], Alo[0].x, Ahi[0].x, Alo[0].y, Ahi[0].y, Bv.x, Bv.y);
            mma16(acc[1][nt], Alo[1].x, Ahi[1].x, Alo[1].y, Ahi[1].y, Bv.x, Bv.y);
        }
        __syncthreads();
        if (k + 2 < 8) stage(k + 2, bf);
        cp_commit();
    }

    float s1 = 0.f, s2 = 0.f;
#pragma unroll
    for (int i = 0; i < 2; i++)
#pragma unroll
        for (int j = 0; j < 8; j++)
#pragma unroll
            for (int l = 0; l < 4; l++) {
                float v = acc[i][j][l];
                s1 += v; s2 += v * v;
            }
#pragma unroll
    for (int off = 16; off > 0; off >>= 1) {
        s1 += __shfl_xor_sync(0xffffffffu, s1, off);
        s2 += __shfl_xor_sync(0xffffffffu, s2, off);
    }
    float* red = smem_all + RED1;
    if (lane == 0) { red[wid * 2] = s1; red[wid * 2 + 1] = s2; }

    float* stg = smem_all;
#pragma unroll
    for (int mt = 0; mt < 2; mt++)
#pragma unroll
        for (int nt = 0; nt < 8; nt++)
#pragma unroll
            for (int j = 0; j < 4; j++) {
                int hcl = ocw * 32 + mt * 16 + q + 8 * (j >> 1);
                int w = nt * 8 + 2 * r + (j & 1);
                stg[hcl * 132 + ph * 64 + w] = acc[mt][nt][j];
            }
    __syncthreads();
    if (tid < 2) {
        float a = red[tid * 8 + 0] + red[tid * 8 + 2] + red[tid * 8 + 4] + red[tid * 8 + 6];
        float bq = red[tid * 8 + 1] + red[tid * 8 + 3] + red[tid * 8 + 5] + red[tid * 8 + 7];
        int slot = b * 8 + ht * 2 + tid;
        g_part1[(slot * 32 + pt) * 2 + 0] = a;
        g_part1[(slot * 32 + pt) * 2 + 1] = bq;
    }
    for (int idx = tid; idx < 4096; idx += 256) {
        int hcl = idx >> 5, p4 = (idx & 31) * 4;
        float4 v = *(const float4*)(stg + hcl * 132 + p4);
        __half2* dst = (__half2*)(g_h1 + (size_t)(b * NHC + ht * 128 + hcl) * HWSZ +
                                  pt * 128 + p4);
        dst[0] = __floats2half2_rn(v.x, v.y);
        dst[1] = __floats2half2_rn(v.z, v.w);
    }
}

// ---------------- dw: one block per (channel, b); compact stride-2 output ---
__global__ __launch_bounds__(256) void k_dw(const float* __restrict__ w_dw,
                                            const float* __restrict__ s1v,
                                            const float* __restrict__ b1v) {
    __shared__ float sa[4356];
    __shared__ float red[512];
    int tid = threadIdx.x;
    int ch = blockIdx.x, b = blockIdx.y;
    float m  = g_ms1[(b * 8 + (ch >> 6)) * 2 + 0];
    float rs = g_ms1[(b * 8 + (ch >> 6)) * 2 + 1];
    float sc = s1v[ch], bi = b1v[ch];
    for (int idx = tid; idx < 4356; idx += 256) sa[idx] = 0.f;
    __syncthreads();
    const __half* src = g_h1 + (size_t)(b * NHC + ch) * 4096;
    for (int idx = tid; idx < 512; idx += 256) {
        int r = idx >> 3, w8 = (idx & 7) * 8;
        __align__(16) __half raw[8];
        *(uint4*)raw = *(const uint4*)(src + r * 64 + w8);
        float* d = sa + (r + 1) * 66 + 1 + w8;
#pragma unroll
        for (int j = 0; j < 8; j++)
            d[j] = silu_f((__half2float(raw[j]) - m) * rs * sc + bi);
    }
    __syncthreads();
    float wd[9];
#pragma unroll
    for (int j = 0; j < 9; j++) wd[j] = w_dw[ch * 9 + j];
    int r = tid >> 2, w0 = (tid & 3) * 16;
    float s1 = 0.f, s2 = 0.f;
    float* orow = g_h2 + (size_t)(b * NHC + ch) * 1024 + (r >> 1) * 32;
    bool reven = (r & 1) == 0;
#pragma unroll
    for (int k = 0; k < 16; k++) {
        int w = w0 + k;
        float a = 0.f;
#pragma unroll
        for (int dr = 0; dr < 3; dr++)
#pragma unroll
            for (int dt = 0; dt < 3; dt++)
                a += sa[(r + dr) * 66 + w + dt] * wd[dr * 3 + dt];
        s1 += a; s2 += a * a;
        if (reven && !(w & 1)) orow[w >> 1] = a;
    }
    red[tid] = s1; red[256 + tid] = s2;
    __syncthreads();
    for (int st = 128; st > 0; st >>= 1) {
        if (tid < st) { red[tid] += red[tid + st]; red[256 + tid] += red[256 + tid + st]; }
        __syncthreads();
    }
    if (tid == 0) {
        int slot = b * 8 + (ch >> 6);
        g_part2[(slot * 64 + (ch & 63)) * 2 + 0] = red[0];
        g_part2[(slot * 64 + (ch & 63)) * 2 + 1] = red[256];
    }
}

// ---------------- pw2 (reads compact h2) ----------------
__global__ __launch_bounds__(256) void k_pw2(const float* __restrict__ w_pw2,
                                             const float* __restrict__ s2v,
                                             const float* __restrict__ b2v) {
    __shared__ float sA[2048], sW[4096], red[512];
    int tid = threadIdx.x;
    int pt = blockIdx.x, b = blockIdx.y;
    int pg = tid & 15, og = tid >> 4;
    float acc[32];
#pragma unroll
    for (int i = 0; i < 32; i++) acc[i] = 0.f;

    for (int c0 = 0; c0 < 512; c0 += 32) {
        __syncthreads();
        for (int idx = tid; idx < 2048; idx += 256) {
            int kc = idx >> 6, p = idx & 63;
            int hc = c0 + kc;
            float v = g_h2[(size_t)(b * NHC + hc) * 1024 + pt * 64 + p];
            float m  = g_ms2[(b * 8 + (hc >> 6)) * 2 + 0];
            float rr = g_ms2[(b * 8 + (hc >> 6)) * 2 + 1];
            float t = (v - m) * rr * s2v[hc] + b2v[hc];
            sA[idx] = silu_f(t);
        }
        for (int idx = tid; idx < 4096; idx += 256) {
            int kc = idx >> 7, co = idx & 127;
            sW[idx] = w_pw2[co * NHC + c0 + kc];
        }
        __syncthreads();
        for (int kc = 0; kc < 32; kc++) {
            float a0 = sA[kc * 64 + 4 * pg + 0];
            float a1 = sA[kc * 64 + 4 * pg + 1];
            float a2 = sA[kc * 64 + 4 * pg + 2];
            float a3 = sA[kc * 64 + 4 * pg + 3];
#pragma unroll
            for (int l = 0; l < 8; l++) {
                float wv = sW[kc * 128 + 8 * og + l];
                acc[0 * 8 + l] += a0 * wv;
                acc[1 * 8 + l] += a1 * wv;
                acc[2 * 8 + l] += a2 * wv;
                acc[3 * 8 + l] += a3 * wv;
            }
        }
    }
    float s1 = 0.f, s2 = 0.f;
#pragma unroll
    for (int i = 0; i < 32; i++) { s1 += acc[i]; s2 += acc[i] * acc[i]; }
    red[tid] = s1; red[256 + tid] = s2;
    __syncthreads();
    if ((tid & 31) == 0) {
        float a = 0.f, bq = 0.f;
        for (int i = 0; i < 32; i++) { a += red[tid + i]; bq += red[256 + tid + i]; }
        int g = tid >> 5;
        g_part3[((b * 8 + g) * 16 + pt) * 2 + 0] = a;
        g_part3[((b * 8 + g) * 16 + pt) * 2 + 1] = bq;
    }
#pragma unroll
    for (int k = 0; k < 4; k++) {
        int pi = pt * 64 + 4 * pg + k;
        int ii = pi >> 5, jj = pi & 31;
#pragma unroll
        for (int l = 0; l < 8; l++) {
            int co = 8 * og + l;
            g_h3[((b * NC + co) << 10) + (ii << 5) + jj] = acc[k * 8 + l];
        }
    }
}

// ---------------- final ----------------
__global__ void k_out(float* __restrict__ out,
                      const float* __restrict__ s3v, const float* __restrict__ b3v) {
    int idx = blockIdx.x * 256 + threadIdx.x;
    int co = (idx >> 10) & 127, b = idx >> 17;
    int g = co >> 4;
    float m  = g_ms3[(b * 8 + g) * 2 + 0];
    float rs = g_ms3[(b * 8 + g) * 2 + 1];
    float t = (g_h3[idx] - m) * rs * s3v[co] + b3v[co];
    out[idx] = silu_f(t);
}

// ---------------- launch ----------------
extern "C" void kernel_launch(void* const* d_in, const int* in_sizes, int n_in,
                              void* d_out, int out_size) {
    const float* x      = (const float*)d_in[0];
    const float* w_exp  = (const float*)d_in[1];
    const float* gs_e   = (const float*)d_in[2];
    const float* gb_e   = (const float*)d_in[3];
    const float* w1     = (const float*)d_in[4];
    const float* b1     = (const float*)d_in[5];
    const float* w2     = (const float*)d_in[6];
    const float* b2     = (const float*)d_in[7];
    const float* w_pw1  = (const float*)d_in[8];
    const float* gn1_s  = (const float*)d_in[9];
    const float* gn1_b  = (const float*)d_in[10];
    const float* w_dw   = (const float*)d_in[11];
    const float* gn2_s  = (const float*)d_in[12];
    const float* gn2_b  = (const float*)d_in[13];
    const float* w_pw2  = (const float*)d_in[14];
    const float* gn3_s  = (const float*)d_in[15];
    const float* gn3_b  = (const float*)d_in[16];
    float* out = (float*)d_out;

    static bool attr_done = false;
    if (!attr_done) {
        cudaFuncSetAttribute(k_expert_mma, cudaFuncAttributeMaxDynamicSharedMemorySize,
                             EXPF * 4);
        cudaFuncSetAttribute(k_pw1_mma, cudaFuncAttributeMaxDynamicSharedMemorySize,
                             PW1F * 4);
        attr_done = true;
    }

    // expert at launch index 3 so ncu's fixed sample lands on it
    k_xform_x<<<2048, 256>>>(x);
    k_xform_w<<<288, 256>>>(w_exp);
    k_router<<<1, 1024>>>(w1, b1, w2, b2);
    k_expert_mma<<<dim3(16, 128), 256, EXPF * 4>>>();
    k_xform_w1<<<16, 256>>>(w_pw1);
    k_finalize<<<4, 256>>>(0);
    k_combine<<<2048, 256>>>(x, gs_e, gb_e);
    k_pw1_mma<<<dim3(4, 32, 16), 256, PW1F * 4>>>();
    k_finalize<<<4, 256>>>(1);
    k_dw<<<dim3(512, 16), 256>>>(w_dw, gn1_s, gn1_b);
    k_finalize<<<4, 256>>>(2);
    k_pw2<<<dim3(16, 16), 256>>>(w_pw2, gn2_s, gn2_b);
    k_finalize<<<4, 256>>>(3);
    k_out<<<8192, 256>>>(out, gn3_s, gn3_b);
}